// round 1
// baseline (speedup 1.0000x reference)
#include <cuda_runtime.h>
#include <math.h>

// ---------------- problem constants ----------------
#define NB    64          // batch
#define LW    128         // windows per sample
#define WW    256         // window size
#define DM    384         // d_model
#define HH    8           // heads
#define EE    48          // head dim
#define DFF   1536
#define NWIN  (NB*LW)     // 8192
#define FEATD 2048        // 64*32

// ---------------- scratch (device globals, alloc-free) ----------------
__device__ float d_feat[NWIN*FEATD];   // 64 MB
__device__ float d_t  [NWIN*DM];
__device__ float d_q  [NWIN*DM];
__device__ float d_k  [NWIN*DM];
__device__ float d_v  [NWIN*DM];
__device__ float d_ao [NWIN*DM];
__device__ float d_buf[NWIN*DM];
__device__ float d_mid[NWIN*DFF];      // 50 MB
__device__ float d_pe [LW*DM];

// ---------------- positional encoding ----------------
__global__ void pe_kernel() {
    int idx = blockIdx.x*blockDim.x + threadIdx.x;
    if (idx >= LW*(DM/2)) return;
    int l = idx / (DM/2);
    int i = idx % (DM/2);
    double ang = (double)l / pow(10000.0, (2.0*i)/(double)DM);
    d_pe[l*DM + 2*i]   = (float)sin(ang);
    d_pe[l*DM + 2*i+1] = (float)cos(ang);
}

// ---------------- fused CNN window encoder ----------------
// one block per window (8192 blocks, 256 threads)
__global__ __launch_bounds__(256) void cnn_kernel(
    const float* __restrict__ x,
    const float* __restrict__ w0, const float* __restrict__ b0,
    const float* __restrict__ w1, const float* __restrict__ b1,
    const float* __restrict__ w2, const float* __restrict__ b2)
{
    __shared__ float sx[256];
    __shared__ float a0[4*128];
    __shared__ float a1[16*64];
    __shared__ float sw0[28];
    __shared__ float sw1[448];
    __shared__ float sw2[7168];
    __shared__ float sb0[4], sb1[16], sb2[64];

    int win = blockIdx.x;
    int tid = threadIdx.x;

    sx[tid] = x[win*256 + tid];
    if (tid < 28) sw0[tid] = w0[tid];
    if (tid < 4)  sb0[tid] = b0[tid];
    for (int i = tid; i < 448; i += 256)  sw1[i] = w1[i];
    if (tid < 16) sb1[tid] = b1[tid];
    for (int i = tid; i < 7168; i += 256) sw2[i] = w2[i];
    if (tid < 64) sb2[tid] = b2[tid];
    __syncthreads();

    // stage 0: conv(1->4,k7,pad3) + relu + maxpool2 : 256 -> 4x128
    for (int it = tid; it < 4*128; it += 256) {
        int c = it >> 7, p = it & 127;
        float acc0 = sb0[c], acc1 = sb0[c];
        #pragma unroll
        for (int k = 0; k < 7; k++) {
            float wv = sw0[c*7+k];
            int i0 = 2*p + k - 3;
            int i1 = i0 + 1;
            if (i0 >= 0 && i0 < 256) acc0 += sx[i0]*wv;
            if (i1 >= 0 && i1 < 256) acc1 += sx[i1]*wv;
        }
        a0[c*128+p] = fmaxf(fmaxf(acc0, acc1), 0.f);
    }
    __syncthreads();

    // stage 1: conv(4->16) + relu + pool : 4x128 -> 16x64
    for (int it = tid; it < 16*64; it += 256) {
        int c = it >> 6, p = it & 63;
        float acc0 = sb1[c], acc1 = sb1[c];
        for (int ci = 0; ci < 4; ci++) {
            const float* wrow = &sw1[(c*4+ci)*7];
            const float* arow = &a0[ci*128];
            #pragma unroll
            for (int k = 0; k < 7; k++) {
                float wv = wrow[k];
                int i0 = 2*p + k - 3;
                int i1 = i0 + 1;
                if (i0 >= 0 && i0 < 128) acc0 += arow[i0]*wv;
                if (i1 >= 0 && i1 < 128) acc1 += arow[i1]*wv;
            }
        }
        a1[c*64+p] = fmaxf(fmaxf(acc0, acc1), 0.f);
    }
    __syncthreads();

    // stage 2: conv(16->64) + relu + pool : 16x64 -> 64x32 -> feat
    for (int it = tid; it < 64*32; it += 256) {
        int c = it >> 5, p = it & 31;
        float acc0 = sb2[c], acc1 = sb2[c];
        for (int ci = 0; ci < 16; ci++) {
            const float* wrow = &sw2[(c*16+ci)*7];
            const float* arow = &a1[ci*64];
            #pragma unroll
            for (int k = 0; k < 7; k++) {
                float wv = wrow[k];
                int i0 = 2*p + k - 3;
                int i1 = i0 + 1;
                if (i0 >= 0 && i0 < 64) acc0 += arow[i0]*wv;
                if (i1 >= 0 && i1 < 64) acc1 += arow[i1]*wv;
            }
        }
        d_feat[win*2048 + c*32 + p] = fmaxf(fmaxf(acc0, acc1), 0.f);
    }
}

// ---------------- SGEMM: C = A(MxK) @ B(KxN) + epilogue ----------------
// epi: 0 = +bias ; 1 = relu(+bias) ; 2 = +bias + extra[r*N+c] ; 3 = relu(+bias) + pe[(r%128)*N+c]
__global__ __launch_bounds__(256) void sgemm_kernel(
    const float* __restrict__ A, const float* __restrict__ B,
    const float* __restrict__ bias, const float* __restrict__ extra,
    float* __restrict__ C, int M, int N, int K, int epi)
{
    __shared__ float As[8][128];
    __shared__ float Bs[8][128];

    int tid = threadIdx.x;
    int bx = blockIdx.x, by = blockIdx.y;
    int tx = tid & 15, ty = tid >> 4;

    float acc[8][8];
    #pragma unroll
    for (int i = 0; i < 8; i++)
        #pragma unroll
        for (int j = 0; j < 8; j++) acc[i][j] = 0.f;

    int arow = tid >> 1, acol4 = (tid & 1) << 2;
    int brow = tid >> 5, bcol  = (tid & 31) << 2;
    const float* Ap = A + (size_t)(by*128 + arow)*K + acol4;
    const float* Bp = B + (size_t)brow*N + bx*128 + bcol;

    for (int k0 = 0; k0 < K; k0 += 8) {
        float4 av = *(const float4*)(Ap + k0);
        float4 bv = *(const float4*)(Bp + (size_t)k0*N);
        __syncthreads();
        As[acol4+0][arow] = av.x;
        As[acol4+1][arow] = av.y;
        As[acol4+2][arow] = av.z;
        As[acol4+3][arow] = av.w;
        *(float4*)&Bs[brow][bcol] = bv;
        __syncthreads();
        #pragma unroll
        for (int kk = 0; kk < 8; kk++) {
            float af[8], bf[8];
            #pragma unroll
            for (int i = 0; i < 8; i++) af[i] = As[kk][ty*8+i];
            #pragma unroll
            for (int j = 0; j < 8; j++) bf[j] = Bs[kk][tx*8+j];
            #pragma unroll
            for (int i = 0; i < 8; i++)
                #pragma unroll
                for (int j = 0; j < 8; j++)
                    acc[i][j] += af[i]*bf[j];
        }
    }

    int row0 = by*128 + ty*8, col0 = bx*128 + tx*8;
    #pragma unroll
    for (int i = 0; i < 8; i++) {
        int r = row0 + i;
        #pragma unroll
        for (int j = 0; j < 8; j++) {
            int c = col0 + j;
            float vv = acc[i][j] + bias[c];
            if      (epi == 1) vv = fmaxf(vv, 0.f);
            else if (epi == 2) vv += extra[(size_t)r*N + c];
            else if (epi == 3) vv = fmaxf(vv, 0.f) + extra[(size_t)(r & 127)*N + c];
            C[(size_t)r*N + c] = vv;
        }
    }
}

// ---------------- fused attention: one block per (n, h) ----------------
__global__ __launch_bounds__(128) void attn_kernel(
    const float* __restrict__ q, const float* __restrict__ k,
    const float* __restrict__ v, float* __restrict__ o)
{
    extern __shared__ float sm[];
    float* Ks = sm;                  // 128*48
    float* Vs = sm + 128*48;         // 128*48
    float* Sc = sm + 2*128*48;       // 128*129

    int n = blockIdx.x, h = blockIdx.y;
    int tid = threadIdx.x;           // 128 = one query per thread

    // cooperative K/V load
    for (int m = tid; m < 128*48; m += 128) {
        int s = m / 48, e = m % 48;
        size_t g = (size_t)(n*128 + s)*DM + h*48 + e;
        Ks[m] = k[g];
        Vs[m] = v[g];
    }
    float qr[48];
    {
        size_t g = (size_t)(n*128 + tid)*DM + h*48;
        #pragma unroll
        for (int e = 0; e < 48; e++) qr[e] = q[g + e];
    }
    __syncthreads();

    const float temp = 1.0f / sqrtf(48.0f);
    float mx = -1e30f;
    float* myrow = &Sc[tid*129];
    for (int s = 0; s < 128; s++) {
        const float* kr = &Ks[s*48];
        float d = 0.f;
        #pragma unroll
        for (int e = 0; e < 48; e++) d += qr[e]*kr[e];
        d *= temp;
        myrow[s] = d;
        mx = fmaxf(mx, d);
    }
    float ssum = 0.f;
    for (int s = 0; s < 128; s++) {
        float p = expf(myrow[s] - mx);
        myrow[s] = p;
        ssum += p;
    }
    float inv = 1.0f / ssum;

    size_t og = (size_t)(n*128 + tid)*DM + h*48;
    #pragma unroll 4
    for (int e = 0; e < 48; e++) {
        float a = 0.f;
        for (int s = 0; s < 128; s++) a += myrow[s]*Vs[s*48+e];
        o[og + e] = a*inv;
    }
}

// ---------------- layernorm over last dim (384), one block per row ----------------
__global__ __launch_bounds__(128) void ln_kernel(
    const float* __restrict__ in, const float* __restrict__ g,
    const float* __restrict__ b, float* __restrict__ out)
{
    __shared__ float red[128];
    int r = blockIdx.x, tid = threadIdx.x;
    const float* row = in + (size_t)r*DM;
    float v0 = row[tid], v1 = row[tid+128], v2 = row[tid+256];

    red[tid] = v0 + v1 + v2;
    __syncthreads();
    for (int st = 64; st > 0; st >>= 1) { if (tid < st) red[tid] += red[tid+st]; __syncthreads(); }
    float mean = red[0] * (1.0f/384.0f);
    __syncthreads();

    float d0 = v0-mean, d1 = v1-mean, d2 = v2-mean;
    red[tid] = d0*d0 + d1*d1 + d2*d2;
    __syncthreads();
    for (int st = 64; st > 0; st >>= 1) { if (tid < st) red[tid] += red[tid+st]; __syncthreads(); }
    float inv = rsqrtf(red[0]*(1.0f/384.0f) + 1e-5f);

    float* orow = out + (size_t)r*DM;
    orow[tid]     = d0*inv*g[tid]     + b[tid];
    orow[tid+128] = d1*inv*g[tid+128] + b[tid+128];
    orow[tid+256] = d2*inv*g[tid+256] + b[tid+256];
}

// ---------------- mean-pool over L + classifier ----------------
__global__ __launch_bounds__(384) void cls_kernel(
    const float* __restrict__ t, const float* __restrict__ w,
    const float* __restrict__ b, float* __restrict__ out)
{
    __shared__ float red[384];
    int n = blockIdx.x, d = threadIdx.x;
    float s = 0.f;
    for (int l = 0; l < 128; l++) s += t[(size_t)(n*128 + l)*DM + d];
    red[d] = (s * (1.0f/128.0f)) * w[d];
    __syncthreads();
    if (d < 128) red[d] += red[d+128] + red[d+256];
    __syncthreads();
    for (int st = 64; st > 0; st >>= 1) { if (d < st) red[d] += red[d+st]; __syncthreads(); }
    if (d == 0) out[n] = red[0] + b[0];
}

// ---------------- launcher ----------------
extern "C" void kernel_launch(void* const* d_in, const int* in_sizes, int n_in,
                              void* d_out, int out_size)
{
    const float* x   = (const float*)d_in[0];
    const float* cw0 = (const float*)d_in[1];
    const float* cb0 = (const float*)d_in[2];
    const float* cw1 = (const float*)d_in[3];
    const float* cb1 = (const float*)d_in[4];
    const float* cw2 = (const float*)d_in[5];
    const float* cb2 = (const float*)d_in[6];
    const float* ew  = (const float*)d_in[7];
    const float* eb  = (const float*)d_in[8];

    const float *Wq,*Wk,*Wv,*Wo,*W1,*W2,*bq,*bk,*bv,*bo,*b1,*b2;
    if (in_sizes[10] == 1536) {
        // signature order: Wq,bq,Wk,bk,Wv,bv,Wo,bo,W1,b1,W2,b2
        Wq=(const float*)d_in[9];  bq=(const float*)d_in[10];
        Wk=(const float*)d_in[11]; bk=(const float*)d_in[12];
        Wv=(const float*)d_in[13]; bv=(const float*)d_in[14];
        Wo=(const float*)d_in[15]; bo=(const float*)d_in[16];
        W1=(const float*)d_in[17]; b1=(const float*)d_in[18];
        W2=(const float*)d_in[19]; b2=(const float*)d_in[20];
    } else {
        // dict order: Wq,Wk,Wv,Wo,W1,W2,bq,bk,bv,bo,b1,b2
        Wq=(const float*)d_in[9];  Wk=(const float*)d_in[10];
        Wv=(const float*)d_in[11]; Wo=(const float*)d_in[12];
        W1=(const float*)d_in[13]; W2=(const float*)d_in[14];
        bq=(const float*)d_in[15]; bk=(const float*)d_in[16];
        bv=(const float*)d_in[17]; bo=(const float*)d_in[18];
        b1=(const float*)d_in[19]; b2=(const float*)d_in[20];
    }
    const float* g1  = (const float*)d_in[21];
    const float* be1 = (const float*)d_in[22];
    const float* g2  = (const float*)d_in[23];
    const float* be2 = (const float*)d_in[24];
    const float* clw = (const float*)d_in[25];
    const float* clb = (const float*)d_in[26];
    float* out = (float*)d_out;

    float *p_feat,*p_t,*p_q,*p_k,*p_v,*p_ao,*p_buf,*p_mid,*p_pe;
    cudaGetSymbolAddress((void**)&p_feat, d_feat);
    cudaGetSymbolAddress((void**)&p_t,   d_t);
    cudaGetSymbolAddress((void**)&p_q,   d_q);
    cudaGetSymbolAddress((void**)&p_k,   d_k);
    cudaGetSymbolAddress((void**)&p_v,   d_v);
    cudaGetSymbolAddress((void**)&p_ao,  d_ao);
    cudaGetSymbolAddress((void**)&p_buf, d_buf);
    cudaGetSymbolAddress((void**)&p_mid, d_mid);
    cudaGetSymbolAddress((void**)&p_pe,  d_pe);

    int attn_smem = (2*128*48 + 128*129) * (int)sizeof(float);   // 115200 B
    cudaFuncSetAttribute(attn_kernel, cudaFuncAttributeMaxDynamicSharedMemorySize, attn_smem);

    // positional encoding + CNN features
    pe_kernel<<<(LW*(DM/2) + 255)/256, 256>>>();
    cnn_kernel<<<NWIN, 256>>>(x, cw0, cb0, cw1, cb1, cw2, cb2);

    // embed: t = relu(feat @ ew + eb) + pe
    sgemm_kernel<<<dim3(DM/128, NWIN/128), 256>>>(p_feat, ew, eb, p_pe, p_t, NWIN, DM, FEATD, 3);

    for (int i = 0; i < 4; i++) {
        const float* wq = Wq + (size_t)i*DM*DM;  const float* vbq = bq + i*DM;
        const float* wk = Wk + (size_t)i*DM*DM;  const float* vbk = bk + i*DM;
        const float* wv = Wv + (size_t)i*DM*DM;  const float* vbv = bv + i*DM;
        const float* wo = Wo + (size_t)i*DM*DM;  const float* vbo = bo + i*DM;
        const float* w1 = W1 + (size_t)i*DM*DFF; const float* vb1 = b1 + i*DFF;
        const float* w2 = W2 + (size_t)i*DFF*DM; const float* vb2 = b2 + i*DM;

        sgemm_kernel<<<dim3(DM/128, NWIN/128), 256>>>(p_t, wq, vbq, nullptr, p_q, NWIN, DM, DM, 0);
        sgemm_kernel<<<dim3(DM/128, NWIN/128), 256>>>(p_t, wk, vbk, nullptr, p_k, NWIN, DM, DM, 0);
        sgemm_kernel<<<dim3(DM/128, NWIN/128), 256>>>(p_t, wv, vbv, nullptr, p_v, NWIN, DM, DM, 0);

        attn_kernel<<<dim3(NB, HH), 128, attn_smem>>>(p_q, p_k, p_v, p_ao);

        // buf = ao @ Wo + bo + t ; t = LN(buf)
        sgemm_kernel<<<dim3(DM/128, NWIN/128), 256>>>(p_ao, wo, vbo, p_t, p_buf, NWIN, DM, DM, 2);
        ln_kernel<<<NWIN, 128>>>(p_buf, g1 + i*DM, be1 + i*DM, p_t);

        // mid = relu(t @ W1 + b1) ; buf = mid @ W2 + b2 + t ; t = LN(buf)
        sgemm_kernel<<<dim3(DFF/128, NWIN/128), 256>>>(p_t, w1, vb1, nullptr, p_mid, NWIN, DFF, DM, 1);
        sgemm_kernel<<<dim3(DM/128, NWIN/128), 256>>>(p_mid, w2, vb2, p_t, p_buf, NWIN, DM, DFF, 2);
        ln_kernel<<<NWIN, 128>>>(p_buf, g2 + i*DM, be2 + i*DM, p_t);
    }

    cls_kernel<<<NB, 384>>>(p_t, clw, clb, out);
}

// round 2
// speedup vs baseline: 1.0573x; 1.0573x over previous
#include <cuda_runtime.h>
#include <math.h>

// ---------------- problem constants ----------------
#define NB    64          // batch
#define LW    128         // windows per sample
#define WW    256         // window size
#define DM    384         // d_model
#define HH    8           // heads
#define EE    48          // head dim
#define DFF   1536
#define NWIN  (NB*LW)     // 8192
#define FEATD 2048        // 64*32

// ---------------- scratch (device globals, alloc-free) ----------------
__device__ float d_feat[NWIN*FEATD];   // 64 MB
__device__ float d_t  [NWIN*DM];
__device__ float d_q  [NWIN*DM];
__device__ float d_k  [NWIN*DM];
__device__ float d_v  [NWIN*DM];
__device__ float d_ao [NWIN*DM];
__device__ float d_buf[NWIN*DM];
__device__ float d_mid[NWIN*DFF];      // 50 MB
__device__ float d_pe [LW*DM];

// ---------------- positional encoding ----------------
__global__ void pe_kernel() {
    int idx = blockIdx.x*blockDim.x + threadIdx.x;
    if (idx >= LW*(DM/2)) return;
    int l = idx / (DM/2);
    int i = idx % (DM/2);
    double ang = (double)l / pow(10000.0, (2.0*i)/(double)DM);
    d_pe[l*DM + 2*i]   = (float)sin(ang);
    d_pe[l*DM + 2*i+1] = (float)cos(ang);
}

// ---------------- fused CNN window encoder ----------------
// one block per window (8192 blocks, 256 threads)
__global__ __launch_bounds__(256) void cnn_kernel(
    const float* __restrict__ x,
    const float* __restrict__ w0, const float* __restrict__ b0,
    const float* __restrict__ w1, const float* __restrict__ b1,
    const float* __restrict__ w2, const float* __restrict__ b2)
{
    __shared__ float sx[256];
    __shared__ float a0[4*128];
    __shared__ float a1[16*64];
    __shared__ float sw0[28];
    __shared__ float sw1[448];
    __shared__ float sw2[7168];
    __shared__ float sb0[4], sb1[16], sb2[64];

    int win = blockIdx.x;
    int tid = threadIdx.x;

    sx[tid] = x[win*256 + tid];
    if (tid < 28) sw0[tid] = w0[tid];
    if (tid < 4)  sb0[tid] = b0[tid];
    for (int i = tid; i < 448; i += 256)  sw1[i] = w1[i];
    if (tid < 16) sb1[tid] = b1[tid];
    for (int i = tid; i < 7168; i += 256) sw2[i] = w2[i];
    if (tid < 64) sb2[tid] = b2[tid];
    __syncthreads();

    // stage 0: conv(1->4,k7,pad3) + relu + maxpool2 : 256 -> 4x128
    for (int it = tid; it < 4*128; it += 256) {
        int c = it >> 7, p = it & 127;
        float acc0 = sb0[c], acc1 = sb0[c];
        #pragma unroll
        for (int k = 0; k < 7; k++) {
            float wv = sw0[c*7+k];
            int i0 = 2*p + k - 3;
            int i1 = i0 + 1;
            if (i0 >= 0 && i0 < 256) acc0 += sx[i0]*wv;
            if (i1 >= 0 && i1 < 256) acc1 += sx[i1]*wv;
        }
        a0[c*128+p] = fmaxf(fmaxf(acc0, acc1), 0.f);
    }
    __syncthreads();

    // stage 1: conv(4->16) + relu + pool : 4x128 -> 16x64
    for (int it = tid; it < 16*64; it += 256) {
        int c = it >> 6, p = it & 63;
        float acc0 = sb1[c], acc1 = sb1[c];
        for (int ci = 0; ci < 4; ci++) {
            const float* wrow = &sw1[(c*4+ci)*7];
            const float* arow = &a0[ci*128];
            #pragma unroll
            for (int k = 0; k < 7; k++) {
                float wv = wrow[k];
                int i0 = 2*p + k - 3;
                int i1 = i0 + 1;
                if (i0 >= 0 && i0 < 128) acc0 += arow[i0]*wv;
                if (i1 >= 0 && i1 < 128) acc1 += arow[i1]*wv;
            }
        }
        a1[c*64+p] = fmaxf(fmaxf(acc0, acc1), 0.f);
    }
    __syncthreads();

    // stage 2: conv(16->64) + relu + pool : 16x64 -> 64x32 -> feat
    for (int it = tid; it < 64*32; it += 256) {
        int c = it >> 5, p = it & 31;
        float acc0 = sb2[c], acc1 = sb2[c];
        for (int ci = 0; ci < 16; ci++) {
            const float* wrow = &sw2[(c*16+ci)*7];
            const float* arow = &a1[ci*64];
            #pragma unroll
            for (int k = 0; k < 7; k++) {
                float wv = wrow[k];
                int i0 = 2*p + k - 3;
                int i1 = i0 + 1;
                if (i0 >= 0 && i0 < 64) acc0 += arow[i0]*wv;
                if (i1 >= 0 && i1 < 64) acc1 += arow[i1]*wv;
            }
        }
        d_feat[win*2048 + c*32 + p] = fmaxf(fmaxf(acc0, acc1), 0.f);
    }
}

// ---------------- SGEMM: C = A(MxK) @ B(KxN) + epilogue ----------------
// epi: 0 = +bias ; 1 = relu(+bias) ; 2 = +bias + extra[r*N+c] ; 3 = relu(+bias) + pe[(r%128)*N+c]
__global__ __launch_bounds__(256) void sgemm_kernel(
    const float* __restrict__ A, const float* __restrict__ B,
    const float* __restrict__ bias, const float* __restrict__ extra,
    float* __restrict__ C, int M, int N, int K, int epi)
{
    __shared__ float As[8][128];
    __shared__ float Bs[8][128];

    int tid = threadIdx.x;
    int bx = blockIdx.x, by = blockIdx.y;
    int tx = tid & 15, ty = tid >> 4;

    float acc[8][8];
    #pragma unroll
    for (int i = 0; i < 8; i++)
        #pragma unroll
        for (int j = 0; j < 8; j++) acc[i][j] = 0.f;

    int arow = tid >> 1, acol4 = (tid & 1) << 2;
    int brow = tid >> 5, bcol  = (tid & 31) << 2;
    const float* Ap = A + (size_t)(by*128 + arow)*K + acol4;
    const float* Bp = B + (size_t)brow*N + bx*128 + bcol;

    for (int k0 = 0; k0 < K; k0 += 8) {
        float4 av = *(const float4*)(Ap + k0);
        float4 bv = *(const float4*)(Bp + (size_t)k0*N);
        __syncthreads();
        As[acol4+0][arow] = av.x;
        As[acol4+1][arow] = av.y;
        As[acol4+2][arow] = av.z;
        As[acol4+3][arow] = av.w;
        *(float4*)&Bs[brow][bcol] = bv;
        __syncthreads();
        #pragma unroll
        for (int kk = 0; kk < 8; kk++) {
            float af[8], bf[8];
            #pragma unroll
            for (int i = 0; i < 8; i++) af[i] = As[kk][ty*8+i];
            #pragma unroll
            for (int j = 0; j < 8; j++) bf[j] = Bs[kk][tx*8+j];
            #pragma unroll
            for (int i = 0; i < 8; i++)
                #pragma unroll
                for (int j = 0; j < 8; j++)
                    acc[i][j] += af[i]*bf[j];
        }
    }

    int row0 = by*128 + ty*8, col0 = bx*128 + tx*8;
    #pragma unroll
    for (int i = 0; i < 8; i++) {
        int r = row0 + i;
        #pragma unroll
        for (int j = 0; j < 8; j++) {
            int c = col0 + j;
            float vv = acc[i][j] + bias[c];
            if      (epi == 1) vv = fmaxf(vv, 0.f);
            else if (epi == 2) vv += extra[(size_t)r*N + c];
            else if (epi == 3) vv = fmaxf(vv, 0.f) + extra[(size_t)(r & 127)*N + c];
            C[(size_t)r*N + c] = vv;
        }
    }
}

// ---------------- fused attention: one block per (n, h) ----------------
__global__ __launch_bounds__(128) void attn_kernel(
    const float* __restrict__ q, const float* __restrict__ k,
    const float* __restrict__ v, float* __restrict__ o)
{
    extern __shared__ float sm[];
    float* Ks = sm;                  // 128*48
    float* Vs = sm + 128*48;         // 128*48
    float* Sc = sm + 2*128*48;       // 128*129

    int n = blockIdx.x, h = blockIdx.y;
    int tid = threadIdx.x;           // 128 = one query per thread

    // cooperative K/V load
    for (int m = tid; m < 128*48; m += 128) {
        int s = m / 48, e = m % 48;
        size_t g = (size_t)(n*128 + s)*DM + h*48 + e;
        Ks[m] = k[g];
        Vs[m] = v[g];
    }
    float qr[48];
    {
        size_t g = (size_t)(n*128 + tid)*DM + h*48;
        #pragma unroll
        for (int e = 0; e < 48; e++) qr[e] = q[g + e];
    }
    __syncthreads();

    const float temp = 1.0f / sqrtf(48.0f);
    float mx = -1e30f;
    float* myrow = &Sc[tid*129];
    for (int s = 0; s < 128; s++) {
        const float* kr = &Ks[s*48];
        float d = 0.f;
        #pragma unroll
        for (int e = 0; e < 48; e++) d += qr[e]*kr[e];
        d *= temp;
        myrow[s] = d;
        mx = fmaxf(mx, d);
    }
    float ssum = 0.f;
    for (int s = 0; s < 128; s++) {
        float p = expf(myrow[s] - mx);
        myrow[s] = p;
        ssum += p;
    }
    float inv = 1.0f / ssum;

    size_t og = (size_t)(n*128 + tid)*DM + h*48;
    #pragma unroll 4
    for (int e = 0; e < 48; e++) {
        float a = 0.f;
        for (int s = 0; s < 128; s++) a += myrow[s]*Vs[s*48+e];
        o[og + e] = a*inv;
    }
}

// ---------------- layernorm over last dim (384), one block per row ----------------
__global__ __launch_bounds__(128) void ln_kernel(
    const float* __restrict__ in, const float* __restrict__ g,
    const float* __restrict__ b, float* __restrict__ out)
{
    __shared__ float red[128];
    int r = blockIdx.x, tid = threadIdx.x;
    const float* row = in + (size_t)r*DM;
    float v0 = row[tid], v1 = row[tid+128], v2 = row[tid+256];

    red[tid] = v0 + v1 + v2;
    __syncthreads();
    for (int st = 64; st > 0; st >>= 1) { if (tid < st) red[tid] += red[tid+st]; __syncthreads(); }
    float mean = red[0] * (1.0f/384.0f);
    __syncthreads();

    float d0 = v0-mean, d1 = v1-mean, d2 = v2-mean;
    red[tid] = d0*d0 + d1*d1 + d2*d2;
    __syncthreads();
    for (int st = 64; st > 0; st >>= 1) { if (tid < st) red[tid] += red[tid+st]; __syncthreads(); }
    float inv = rsqrtf(red[0]*(1.0f/384.0f) + 1e-5f);

    float* orow = out + (size_t)r*DM;
    orow[tid]     = d0*inv*g[tid]     + b[tid];
    orow[tid+128] = d1*inv*g[tid+128] + b[tid+128];
    orow[tid+256] = d2*inv*g[tid+256] + b[tid+256];
}

// ---------------- mean-pool over L + classifier ----------------
__global__ __launch_bounds__(384) void cls_kernel(
    const float* __restrict__ t, const float* __restrict__ w,
    const float* __restrict__ b, float* __restrict__ out)
{
    __shared__ float red[384];
    int n = blockIdx.x, d = threadIdx.x;
    float s = 0.f;
    for (int l = 0; l < 128; l++) s += t[(size_t)(n*128 + l)*DM + d];
    red[d] = (s * (1.0f/128.0f)) * w[d];
    __syncthreads();
    if (d < 128) red[d] += red[d+128] + red[d+256];
    __syncthreads();
    for (int st = 64; st > 0; st >>= 1) { if (d < st) red[d] += red[d+st]; __syncthreads(); }
    if (d == 0) out[n] = red[0] + b[0];
}

// ---------------- launcher ----------------
extern "C" void kernel_launch(void* const* d_in, const int* in_sizes, int n_in,
                              void* d_out, int out_size)
{
    const float* x   = (const float*)d_in[0];
    const float* cw0 = (const float*)d_in[1];
    const float* cb0 = (const float*)d_in[2];
    const float* cw1 = (const float*)d_in[3];
    const float* cb1 = (const float*)d_in[4];
    const float* cw2 = (const float*)d_in[5];
    const float* cb2 = (const float*)d_in[6];
    const float* ew  = (const float*)d_in[7];
    const float* eb  = (const float*)d_in[8];

    const float *Wq,*Wk,*Wv,*Wo,*W1,*W2,*bq,*bk,*bv,*bo,*b1,*b2;
    if (in_sizes[10] == 1536) {
        // signature order: Wq,bq,Wk,bk,Wv,bv,Wo,bo,W1,b1,W2,b2
        Wq=(const float*)d_in[9];  bq=(const float*)d_in[10];
        Wk=(const float*)d_in[11]; bk=(const float*)d_in[12];
        Wv=(const float*)d_in[13]; bv=(const float*)d_in[14];
        Wo=(const float*)d_in[15]; bo=(const float*)d_in[16];
        W1=(const float*)d_in[17]; b1=(const float*)d_in[18];
        W2=(const float*)d_in[19]; b2=(const float*)d_in[20];
    } else {
        // dict order: Wq,Wk,Wv,Wo,W1,W2,bq,bk,bv,bo,b1,b2
        Wq=(const float*)d_in[9];  Wk=(const float*)d_in[10];
        Wv=(const float*)d_in[11]; Wo=(const float*)d_in[12];
        W1=(const float*)d_in[13]; W2=(const float*)d_in[14];
        bq=(const float*)d_in[15]; bk=(const float*)d_in[16];
        bv=(const float*)d_in[17]; bo=(const float*)d_in[18];
        b1=(const float*)d_in[19]; b2=(const float*)d_in[20];
    }
    const float* g1  = (const float*)d_in[21];
    const float* be1 = (const float*)d_in[22];
    const float* g2  = (const float*)d_in[23];
    const float* be2 = (const float*)d_in[24];
    const float* clw = (const float*)d_in[25];
    const float* clb = (const float*)d_in[26];
    float* out = (float*)d_out;

    float *p_feat,*p_t,*p_q,*p_k,*p_v,*p_ao,*p_buf,*p_mid,*p_pe;
    cudaGetSymbolAddress((void**)&p_feat, d_feat);
    cudaGetSymbolAddress((void**)&p_t,   d_t);
    cudaGetSymbolAddress((void**)&p_q,   d_q);
    cudaGetSymbolAddress((void**)&p_k,   d_k);
    cudaGetSymbolAddress((void**)&p_v,   d_v);
    cudaGetSymbolAddress((void**)&p_ao,  d_ao);
    cudaGetSymbolAddress((void**)&p_buf, d_buf);
    cudaGetSymbolAddress((void**)&p_mid, d_mid);
    cudaGetSymbolAddress((void**)&p_pe,  d_pe);

    int attn_smem = (2*128*48 + 128*129) * (int)sizeof(float);   // 115200 B
    cudaFuncSetAttribute(attn_kernel, cudaFuncAttributeMaxDynamicSharedMemorySize, attn_smem);

    // positional encoding + CNN features
    pe_kernel<<<(LW*(DM/2) + 255)/256, 256>>>();
    cnn_kernel<<<NWIN, 256>>>(x, cw0, cb0, cw1, cb1, cw2, cb2);

    // embed: t = relu(feat @ ew + eb) + pe
    sgemm_kernel<<<dim3(DM/128, NWIN/128), 256>>>(p_feat, ew, eb, p_pe, p_t, NWIN, DM, FEATD, 3);

    for (int i = 0; i < 4; i++) {
        const float* wq = Wq + (size_t)i*DM*DM;  const float* vbq = bq + i*DM;
        const float* wk = Wk + (size_t)i*DM*DM;  const float* vbk = bk + i*DM;
        const float* wv = Wv + (size_t)i*DM*DM;  const float* vbv = bv + i*DM;
        const float* wo = Wo + (size_t)i*DM*DM;  const float* vbo = bo + i*DM;
        const float* w1 = W1 + (size_t)i*DM*DFF; const float* vb1 = b1 + i*DFF;
        const float* w2 = W2 + (size_t)i*DFF*DM; const float* vb2 = b2 + i*DM;

        sgemm_kernel<<<dim3(DM/128, NWIN/128), 256>>>(p_t, wq, vbq, nullptr, p_q, NWIN, DM, DM, 0);
        sgemm_kernel<<<dim3(DM/128, NWIN/128), 256>>>(p_t, wk, vbk, nullptr, p_k, NWIN, DM, DM, 0);
        sgemm_kernel<<<dim3(DM/128, NWIN/128), 256>>>(p_t, wv, vbv, nullptr, p_v, NWIN, DM, DM, 0);

        attn_kernel<<<dim3(NB, HH), 128, attn_smem>>>(p_q, p_k, p_v, p_ao);

        // buf = ao @ Wo + bo + t ; t = LN(buf)
        sgemm_kernel<<<dim3(DM/128, NWIN/128), 256>>>(p_ao, wo, vbo, p_t, p_buf, NWIN, DM, DM, 2);
        ln_kernel<<<NWIN, 128>>>(p_buf, g1 + i*DM, be1 + i*DM, p_t);

        // mid = relu(t @ W1 + b1) ; buf = mid @ W2 + b2 + t ; t = LN(buf)
        sgemm_kernel<<<dim3(DFF/128, NWIN/128), 256>>>(p_t, w1, vb1, nullptr, p_mid, NWIN, DFF, DM, 1);
        sgemm_kernel<<<dim3(DM/128, NWIN/128), 256>>>(p_mid, w2, vb2, p_t, p_buf, NWIN, DM, DFF, 2);
        ln_kernel<<<NWIN, 128>>>(p_buf, g2 + i*DM, be2 + i*DM, p_t);
    }

    cls_kernel<<<NB, 384>>>(p_t, clw, clb, out);
}

// round 4
// speedup vs baseline: 3.2420x; 3.0662x over previous
#include <cuda_runtime.h>
#include <math.h>
#include <stdint.h>

// ---------------- problem constants ----------------
#define NB    64
#define LW    128
#define DM    384
#define HH    8
#define DFF   1536
#define NWIN  (NB*LW)     // 8192
#define FEATD 2048

// ---------------- scratch (device globals, alloc-free) ----------------
__device__ float d_feat[NWIN*FEATD];
__device__ float d_t  [NWIN*DM];
__device__ float d_q  [NWIN*DM];
__device__ float d_k  [NWIN*DM];
__device__ float d_v  [NWIN*DM];
__device__ float d_ao [NWIN*DM];
__device__ float d_buf[NWIN*DM];
__device__ float d_mid[NWIN*DFF];
__device__ float d_pe [LW*DM];
__device__ float d_bt_embed[DM*FEATD];
__device__ float d_btq[4][DM*DM];
__device__ float d_btk[4][DM*DM];
__device__ float d_btv[4][DM*DM];
__device__ float d_bto[4][DM*DM];
__device__ float d_bt1[4][DFF*DM];
__device__ float d_bt2[4][DM*DFF];

// ---------------- helpers ----------------
__device__ __forceinline__ uint32_t smem_u32(const void* p) {
    uint32_t a;
    asm("{ .reg .u64 t; cvta.to.shared.u64 t, %1; cvt.u32.u64 %0, t; }" : "=r"(a) : "l"(p));
    return a;
}
__device__ __forceinline__ uint32_t tf32_bits(float x) {
    uint32_t u; asm("cvt.rna.tf32.f32 %0, %1;" : "=r"(u) : "f"(x)); return u;
}
__device__ __forceinline__ float tf32r(float x) { return __uint_as_float(tf32_bits(x)); }

__device__ __forceinline__ void cp16(uint32_t s, const void* g) {
    asm volatile("cp.async.cg.shared.global [%0], [%1], 16;" :: "r"(s), "l"(g));
}
__device__ __forceinline__ void cp_commit() { asm volatile("cp.async.commit_group;"); }
template<int N> __device__ __forceinline__ void cp_wait() {
    asm volatile("cp.async.wait_group %0;" :: "n"(N));
}
__device__ __forceinline__ void ldsm4(uint32_t* r, uint32_t addr) {
    asm volatile("ldmatrix.sync.aligned.m8n8.x4.shared.b16 {%0,%1,%2,%3}, [%4];"
        : "=r"(r[0]), "=r"(r[1]), "=r"(r[2]), "=r"(r[3]) : "r"(addr));
}
__device__ __forceinline__ void mma8(float* c, const uint32_t* a, const uint32_t* b) {
    asm volatile("mma.sync.aligned.m16n8k8.row.col.f32.tf32.tf32.f32 "
        "{%0,%1,%2,%3}, {%4,%5,%6,%7}, {%8,%9}, {%0,%1,%2,%3};"
        : "+f"(c[0]), "+f"(c[1]), "+f"(c[2]), "+f"(c[3])
        : "r"(a[0]), "r"(a[1]), "r"(a[2]), "r"(a[3]), "r"(b[0]), "r"(b[1]));
}

// SMEM geometry: per stage, A tile [128][36] + B tile [128][36] floats (rows padded 32->36)
#define ROWB   144            // 36 floats * 4B
#define TILEB  18432          // 128 * 144
#define STAGEB 36864          // A + B
#define GSMEM  (2*STAGEB)     // 73728

// ---------------- mma.sync TF32 GEMM core: C tile 128x128, K chunks of 32 ----------------
// epi: 0=+bias ; 1=relu(+bias) ; 2=+bias+extra[m*ldc+c] ; 3=relu(+bias)+pe[(m&127)*ldc+c]
__device__ __forceinline__ void gemm_core(
    const float* __restrict__ A, const float* __restrict__ BtBlk,
    const float* __restrict__ bias, const float* __restrict__ extra,
    float* __restrict__ C, int K, int ldc, int epi, int row0, int col0)
{
    extern __shared__ float sm[];
    uint32_t sbase = smem_u32(sm);
    int tid = threadIdx.x;

    // copy geometry: 1024 float4 per tile, 4 per thread, 32-row strides
    int crow = tid >> 3, ccol4 = tid & 7;
    const float* Ag = A + (size_t)(row0 + crow) * K + ccol4 * 4;
    const float* Bg = BtBlk + (size_t)crow * K + ccol4 * 4;
    uint32_t sA = sbase + crow * ROWB + ccol4 * 16;
    uint32_t sB = sA + TILEB;
    int nk = K >> 5;

    // prologue: stage 0 = chunk 0
    #pragma unroll
    for (int i = 0; i < 4; i++) {
        cp16(sA + i * 32 * ROWB, Ag + (size_t)(i * 32) * K);
        cp16(sB + i * 32 * ROWB, Bg + (size_t)(i * 32) * K);
    }
    cp_commit();

    // fragment geometry
    int lane = tid & 31, w = tid >> 5, wm = w & 1, wn = w >> 1;
    int g = lane >> 3, lr = lane & 7;
    uint32_t aoff = sbase + ((wm * 64 + (g & 1) * 8 + lr) * 36 + (g >> 1) * 4) * 4;
    uint32_t boff = sbase + TILEB + ((wn * 32 + (g >> 1) * 8 + lr) * 36 + (g & 1) * 4) * 4;

    float c[4][4][4];
    #pragma unroll
    for (int i = 0; i < 4; i++)
        #pragma unroll
        for (int j = 0; j < 4; j++)
            #pragma unroll
            for (int q = 0; q < 4; q++) c[i][j][q] = 0.f;

    for (int kc = 0; kc < nk; kc++) {
        int st = kc & 1;
        if (kc + 1 < nk) {
            uint32_t off = ((kc + 1) & 1) * STAGEB;
            const float* ag = Ag + (size_t)(kc + 1) * 32;
            const float* bg = Bg + (size_t)(kc + 1) * 32;
            #pragma unroll
            for (int i = 0; i < 4; i++) {
                cp16(sA + off + i * 32 * ROWB, ag + (size_t)(i * 32) * K);
                cp16(sB + off + i * 32 * ROWB, bg + (size_t)(i * 32) * K);
            }
        }
        cp_commit();
        cp_wait<1>();
        __syncthreads();

        uint32_t ab = aoff + st * STAGEB;
        uint32_t bb = boff + st * STAGEB;
        #pragma unroll
        for (int ks = 0; ks < 4; ks++) {
            uint32_t af[4][4], bf[2][4];
            #pragma unroll
            for (int mf = 0; mf < 4; mf++)
                ldsm4(af[mf], ab + mf * 16 * ROWB + ks * 32);
            #pragma unroll
            for (int np = 0; np < 2; np++)
                ldsm4(bf[np], bb + np * 16 * ROWB + ks * 32);
            #pragma unroll
            for (int mf = 0; mf < 4; mf++)
                #pragma unroll
                for (int nf = 0; nf < 4; nf++)
                    mma8(c[mf][nf], af[mf], &bf[nf >> 1][(nf & 1) * 2]);
        }
        __syncthreads();
    }

    // epilogue (tf32-rna rounded outputs)
    #pragma unroll
    for (int mf = 0; mf < 4; mf++) {
        #pragma unroll
        for (int half = 0; half < 2; half++) {
            int r = row0 + wm * 64 + mf * 16 + (lane >> 2) + half * 8;
            float* crow = C + (size_t)r * ldc;
            const float* exrow = nullptr;
            if (epi == 2)      exrow = extra + (size_t)r * ldc;
            else if (epi == 3) exrow = extra + (size_t)(r & (LW - 1)) * ldc;
            #pragma unroll
            for (int nf = 0; nf < 4; nf++) {
                int col = col0 + wn * 32 + nf * 8 + (lane & 3) * 2;
                float v0 = c[mf][nf][half * 2 + 0] + bias[col];
                float v1 = c[mf][nf][half * 2 + 1] + bias[col + 1];
                if (epi == 1) { v0 = fmaxf(v0, 0.f); v1 = fmaxf(v1, 0.f); }
                else if (epi == 2) { v0 += exrow[col]; v1 += exrow[col + 1]; }
                else if (epi == 3) {
                    v0 = fmaxf(v0, 0.f) + exrow[col];
                    v1 = fmaxf(v1, 0.f) + exrow[col + 1];
                }
                float2 o = make_float2(tf32r(v0), tf32r(v1));
                *(float2*)(crow + col) = o;
            }
        }
    }
}

__global__ __launch_bounds__(256) void gemm_mma(
    const float* __restrict__ A, const float* __restrict__ Bt,
    const float* __restrict__ bias, const float* __restrict__ extra,
    float* __restrict__ C, int K, int N, int epi)
{
    gemm_core(A, Bt + (size_t)blockIdx.x * 128 * K, bias, extra, C, K, N, epi,
              blockIdx.y * 128, blockIdx.x * 128);
}

__global__ __launch_bounds__(256) void gemm_mma_qkv(
    const float* __restrict__ A,
    const float* __restrict__ btq, const float* __restrict__ btk, const float* __restrict__ btv,
    const float* __restrict__ bqv, const float* __restrict__ bkv, const float* __restrict__ bvv,
    float* __restrict__ q, float* __restrict__ k, float* __restrict__ v)
{
    int sel = blockIdx.x / 3, j = blockIdx.x % 3;
    const float* Bt   = sel == 0 ? btq : (sel == 1 ? btk : btv);
    const float* bias = sel == 0 ? bqv : (sel == 1 ? bkv : bvv);
    float*       C    = sel == 0 ? q   : (sel == 1 ? k   : v);
    gemm_core(A, Bt + (size_t)j * 128 * DM, bias, nullptr, C, DM, DM, 0,
              blockIdx.y * 128, j * 128);
}

// ---------------- weight transpose with tf32-rna rounding: out[n][k] = tf32(in[k][n]) ----------------
__global__ void transpose_tf32(const float* __restrict__ in, float* __restrict__ out, int Kd, int Nd)
{
    __shared__ float tile[32][33];
    int kb = blockIdx.x * 32, nb = blockIdx.y * 32;
    int tx = threadIdx.x, ty = threadIdx.y;
    #pragma unroll
    for (int j = 0; j < 32; j += 8)
        tile[ty + j][tx] = in[(size_t)(kb + ty + j) * Nd + nb + tx];
    __syncthreads();
    #pragma unroll
    for (int j = 0; j < 32; j += 8)
        out[(size_t)(nb + ty + j) * Kd + kb + tx] = tf32r(tile[tx][ty + j]);
}

// ---------------- positional encoding ----------------
__global__ void pe_kernel() {
    int idx = blockIdx.x * blockDim.x + threadIdx.x;
    if (idx >= LW * (DM / 2)) return;
    int l = idx / (DM / 2);
    int i = idx % (DM / 2);
    double ang = (double)l / pow(10000.0, (2.0 * i) / (double)DM);
    d_pe[l * DM + 2 * i]     = (float)sin(ang);
    d_pe[l * DM + 2 * i + 1] = (float)cos(ang);
}

// ---------------- fused CNN window encoder: one block per window ----------------
__global__ __launch_bounds__(256) void cnn_kernel(
    const float* __restrict__ x,
    const float* __restrict__ w0, const float* __restrict__ b0,
    const float* __restrict__ w1, const float* __restrict__ b1,
    const float* __restrict__ w2, const float* __restrict__ b2)
{
    __shared__ float sx[256];
    __shared__ float a0[4 * 128];
    __shared__ float a1[16 * 64];
    __shared__ float sw0[28];
    __shared__ float sw1[448];
    __shared__ float sw2t[112 * 64];     // [ci*7+k][c] transposed
    __shared__ float sb0[4], sb1[16], sb2[64];

    int win = blockIdx.x;
    int tid = threadIdx.x;

    sx[tid] = x[win * 256 + tid];
    if (tid < 28) sw0[tid] = w0[tid];
    if (tid < 4)  sb0[tid] = b0[tid];
    for (int i = tid; i < 448; i += 256) sw1[i] = w1[i];
    if (tid < 16) sb1[tid] = b1[tid];
    for (int i = tid; i < 7168; i += 256) {
        int c = i / 112, r = i % 112;
        sw2t[r * 64 + c] = w2[i];
    }
    if (tid < 64) sb2[tid] = b2[tid];
    __syncthreads();

    // stage 0: conv(1->4,k7,p3)+relu+pool2 : 256 -> 4x128
    for (int it = tid; it < 4 * 128; it += 256) {
        int c = it >> 7, p = it & 127;
        float acc0 = sb0[c], acc1 = sb0[c];
        #pragma unroll
        for (int k = 0; k < 7; k++) {
            float wv = sw0[c * 7 + k];
            int i0 = 2 * p + k - 3, i1 = i0 + 1;
            if (i0 >= 0 && i0 < 256) acc0 += sx[i0] * wv;
            if (i1 >= 0 && i1 < 256) acc1 += sx[i1] * wv;
        }
        a0[c * 128 + p] = fmaxf(fmaxf(acc0, acc1), 0.f);
    }
    __syncthreads();

    // stage 1: conv(4->16)+relu+pool : 4x128 -> 16x64
    for (int it = tid; it < 16 * 64; it += 256) {
        int c = it >> 6, p = it & 63;
        float acc0 = sb1[c], acc1 = sb1[c];
        for (int ci = 0; ci < 4; ci++) {
            const float* wrow = &sw1[(c * 4 + ci) * 7];
            const float* arow = &a0[ci * 128];
            #pragma unroll
            for (int k = 0; k < 7; k++) {
                float wv = wrow[k];
                int i0 = 2 * p + k - 3, i1 = i0 + 1;
                if (i0 >= 0 && i0 < 128) acc0 += arow[i0] * wv;
                if (i1 >= 0 && i1 < 128) acc1 += arow[i1] * wv;
            }
        }
        a1[c * 64 + p] = fmaxf(fmaxf(acc0, acc1), 0.f);
    }
    __syncthreads();

    // stage 2: conv(16->64)+relu+pool : 16x64 -> 64x32, register-blocked
    {
        int c = tid & 63, g = tid >> 6;
        float acc0[8], acc1[8];
        #pragma unroll
        for (int p = 0; p < 8; p++) { acc0[p] = sb2[c]; acc1[p] = sb2[c]; }
        int base = 16 * g - 3;
        for (int ci = 0; ci < 16; ci++) {
            float xin[22];
            #pragma unroll
            for (int j = 0; j < 22; j++) {
                int idx = base + j;
                xin[j] = (idx >= 0 && idx < 64) ? a1[ci * 64 + idx] : 0.f;
            }
            float wv[7];
            #pragma unroll
            for (int k = 0; k < 7; k++) wv[k] = sw2t[(ci * 7 + k) * 64 + c];
            #pragma unroll
            for (int p = 0; p < 8; p++) {
                #pragma unroll
                for (int k = 0; k < 7; k++) {
                    acc0[p] += wv[k] * xin[2 * p + k];
                    acc1[p] += wv[k] * xin[2 * p + k + 1];
                }
            }
        }
        float o[8];
        #pragma unroll
        for (int p = 0; p < 8; p++) o[p] = tf32r(fmaxf(fmaxf(acc0[p], acc1[p]), 0.f));
        float* dst = &d_feat[(size_t)win * 2048 + c * 32 + g * 8];
        *(float4*)(dst)     = *(const float4*)(o);
        *(float4*)(dst + 4) = *(const float4*)(o + 4);
    }
}

// ---------------- fused attention: one block per (n, h), one query per thread ----------------
__global__ __launch_bounds__(128) void attn_kernel(
    const float* __restrict__ q, const float* __restrict__ k,
    const float* __restrict__ v, float* __restrict__ o)
{
    extern __shared__ float sma[];
    float* Ks = sma;                  // 128*48
    float* Vs = sma + 6144;
    float* Sc = sma + 12288;          // 128*129

    int n = blockIdx.x, h = blockIdx.y;
    int tid = threadIdx.x;

    for (int m4 = tid; m4 < 1536; m4 += 128) {
        int s = m4 / 12, j = m4 % 12;
        size_t gg = ((size_t)(n * 128 + s) * DM + h * 48) / 4 + j;
        ((float4*)Ks)[s * 12 + j] = ((const float4*)k)[gg];
        ((float4*)Vs)[s * 12 + j] = ((const float4*)v)[gg];
    }
    float4 qr[12];
    {
        const float4* qp = (const float4*)(q + (size_t)(n * 128 + tid) * DM + h * 48);
        #pragma unroll
        for (int j = 0; j < 12; j++) qr[j] = qp[j];
    }
    __syncthreads();

    const float temp = 0.14433756729740643f;   // 1/sqrt(48)
    float mx = -1e30f;
    float* myrow = &Sc[tid * 129];
    for (int s = 0; s < 128; s++) {
        const float4* kr = (const float4*)&Ks[s * 48];
        float d = 0.f;
        #pragma unroll
        for (int j = 0; j < 12; j++) {
            float4 a = qr[j], b = kr[j];
            d += a.x * b.x + a.y * b.y + a.z * b.z + a.w * b.w;
        }
        d *= temp;
        myrow[s] = d;
        mx = fmaxf(mx, d);
    }
    float ssum = 0.f;
    for (int s = 0; s < 128; s++) {
        float p = __expf(myrow[s] - mx);
        myrow[s] = p;
        ssum += p;
    }
    float inv = 1.0f / ssum;

    float4 acc[12];
    #pragma unroll
    for (int j = 0; j < 12; j++) acc[j] = make_float4(0.f, 0.f, 0.f, 0.f);
    for (int s = 0; s < 128; s++) {
        float p = myrow[s];
        const float4* vr = (const float4*)&Vs[s * 48];
        #pragma unroll
        for (int j = 0; j < 12; j++) {
            float4 b = vr[j];
            acc[j].x += p * b.x; acc[j].y += p * b.y;
            acc[j].z += p * b.z; acc[j].w += p * b.w;
        }
    }
    float4* op = (float4*)(o + (size_t)(n * 128 + tid) * DM + h * 48);
    #pragma unroll
    for (int j = 0; j < 12; j++)
        op[j] = make_float4(tf32r(acc[j].x * inv), tf32r(acc[j].y * inv),
                            tf32r(acc[j].z * inv), tf32r(acc[j].w * inv));
}

// ---------------- layernorm (384), one block per row ----------------
__global__ __launch_bounds__(128) void ln_kernel(
    const float* __restrict__ in, const float* __restrict__ g,
    const float* __restrict__ b, float* __restrict__ out)
{
    __shared__ float red[128];
    int r = blockIdx.x, tid = threadIdx.x;
    const float* row = in + (size_t)r * DM;
    float v0 = row[tid], v1 = row[tid + 128], v2 = row[tid + 256];

    red[tid] = v0 + v1 + v2;
    __syncthreads();
    for (int st = 64; st > 0; st >>= 1) { if (tid < st) red[tid] += red[tid + st]; __syncthreads(); }
    float mean = red[0] * (1.0f / 384.0f);
    __syncthreads();

    float d0 = v0 - mean, d1 = v1 - mean, d2 = v2 - mean;
    red[tid] = d0 * d0 + d1 * d1 + d2 * d2;
    __syncthreads();
    for (int st = 64; st > 0; st >>= 1) { if (tid < st) red[tid] += red[tid + st]; __syncthreads(); }
    float inv = rsqrtf(red[0] * (1.0f / 384.0f) + 1e-5f);

    float* orow = out + (size_t)r * DM;
    orow[tid]       = tf32r(d0 * inv * g[tid]       + b[tid]);
    orow[tid + 128] = tf32r(d1 * inv * g[tid + 128] + b[tid + 128]);
    orow[tid + 256] = tf32r(d2 * inv * g[tid + 256] + b[tid + 256]);
}

// ---------------- mean-pool over L + classifier ----------------
__global__ __launch_bounds__(384) void cls_kernel(
    const float* __restrict__ t, const float* __restrict__ w,
    const float* __restrict__ b, float* __restrict__ out)
{
    __shared__ float red[384];
    int n = blockIdx.x, d = threadIdx.x;
    float s = 0.f;
    for (int l = 0; l < 128; l++) s += t[(size_t)(n * 128 + l) * DM + d];
    red[d] = (s * (1.0f / 128.0f)) * w[d];
    __syncthreads();
    if (d < 128) red[d] += red[d + 128] + red[d + 256];
    __syncthreads();
    for (int st = 64; st > 0; st >>= 1) { if (d < st) red[d] += red[d + st]; __syncthreads(); }
    if (d == 0) out[n] = red[0] + b[0];
}

// ---------------- launcher ----------------
extern "C" void kernel_launch(void* const* d_in, const int* in_sizes, int n_in,
                              void* d_out, int out_size)
{
    const float* x   = (const float*)d_in[0];
    const float* cw0 = (const float*)d_in[1];
    const float* cb0 = (const float*)d_in[2];
    const float* cw1 = (const float*)d_in[3];
    const float* cb1 = (const float*)d_in[4];
    const float* cw2 = (const float*)d_in[5];
    const float* cb2 = (const float*)d_in[6];
    const float* ew  = (const float*)d_in[7];
    const float* eb  = (const float*)d_in[8];

    const float *Wq,*Wk,*Wv,*Wo,*W1,*W2,*bq,*bk,*bv,*bo,*b1,*b2;
    if (in_sizes[10] == 1536) {
        Wq=(const float*)d_in[9];  bq=(const float*)d_in[10];
        Wk=(const float*)d_in[11]; bk=(const float*)d_in[12];
        Wv=(const float*)d_in[13]; bv=(const float*)d_in[14];
        Wo=(const float*)d_in[15]; bo=(const float*)d_in[16];
        W1=(const float*)d_in[17]; b1=(const float*)d_in[18];
        W2=(const float*)d_in[19]; b2=(const float*)d_in[20];
    } else {
        Wq=(const float*)d_in[9];  Wk=(const float*)d_in[10];
        Wv=(const float*)d_in[11]; Wo=(const float*)d_in[12];
        W1=(const float*)d_in[13]; W2=(const float*)d_in[14];
        bq=(const float*)d_in[15]; bk=(const float*)d_in[16];
        bv=(const float*)d_in[17]; bo=(const float*)d_in[18];
        b1=(const float*)d_in[19]; b2=(const float*)d_in[20];
    }
    const float* g1  = (const float*)d_in[21];
    const float* be1 = (const float*)d_in[22];
    const float* g2  = (const float*)d_in[23];
    const float* be2 = (const float*)d_in[24];
    const float* clw = (const float*)d_in[25];
    const float* clb = (const float*)d_in[26];
    float* out = (float*)d_out;

    float *p_feat,*p_t,*p_q,*p_k,*p_v,*p_ao,*p_buf,*p_mid,*p_pe;
    float *p_bte,*p_btq,*p_btk,*p_btv,*p_bto,*p_bt1,*p_bt2;
    cudaGetSymbolAddress((void**)&p_feat, d_feat);
    cudaGetSymbolAddress((void**)&p_t,   d_t);
    cudaGetSymbolAddress((void**)&p_q,   d_q);
    cudaGetSymbolAddress((void**)&p_k,   d_k);
    cudaGetSymbolAddress((void**)&p_v,   d_v);
    cudaGetSymbolAddress((void**)&p_ao,  d_ao);
    cudaGetSymbolAddress((void**)&p_buf, d_buf);
    cudaGetSymbolAddress((void**)&p_mid, d_mid);
    cudaGetSymbolAddress((void**)&p_pe,  d_pe);
    cudaGetSymbolAddress((void**)&p_bte, d_bt_embed);
    cudaGetSymbolAddress((void**)&p_btq, d_btq);
    cudaGetSymbolAddress((void**)&p_btk, d_btk);
    cudaGetSymbolAddress((void**)&p_btv, d_btv);
    cudaGetSymbolAddress((void**)&p_bto, d_bto);
    cudaGetSymbolAddress((void**)&p_bt1, d_bt1);
    cudaGetSymbolAddress((void**)&p_bt2, d_bt2);

    int attn_smem = (2*128*48 + 128*129) * (int)sizeof(float);   // 115200 B
    cudaFuncSetAttribute(attn_kernel, cudaFuncAttributeMaxDynamicSharedMemorySize, attn_smem);
    cudaFuncSetAttribute(gemm_mma,     cudaFuncAttributeMaxDynamicSharedMemorySize, GSMEM);
    cudaFuncSetAttribute(gemm_mma_qkv, cudaFuncAttributeMaxDynamicSharedMemorySize, GSMEM);

    dim3 tb(32, 8);
    transpose_tf32<<<dim3(FEATD/32, DM/32), tb>>>(ew, p_bte, FEATD, DM);
    for (int i = 0; i < 4; i++) {
        transpose_tf32<<<dim3(DM/32, DM/32), tb>>>(Wq + (size_t)i*DM*DM,  p_btq + (size_t)i*DM*DM,  DM, DM);
        transpose_tf32<<<dim3(DM/32, DM/32), tb>>>(Wk + (size_t)i*DM*DM,  p_btk + (size_t)i*DM*DM,  DM, DM);
        transpose_tf32<<<dim3(DM/32, DM/32), tb>>>(Wv + (size_t)i*DM*DM,  p_btv + (size_t)i*DM*DM,  DM, DM);
        transpose_tf32<<<dim3(DM/32, DM/32), tb>>>(Wo + (size_t)i*DM*DM,  p_bto + (size_t)i*DM*DM,  DM, DM);
        transpose_tf32<<<dim3(DM/32, DFF/32), tb>>>(W1 + (size_t)i*DM*DFF, p_bt1 + (size_t)i*DFF*DM, DM, DFF);
        transpose_tf32<<<dim3(DFF/32, DM/32), tb>>>(W2 + (size_t)i*DFF*DM, p_bt2 + (size_t)i*DM*DFF, DFF, DM);
    }

    pe_kernel<<<(LW*(DM/2) + 255)/256, 256>>>();
    cnn_kernel<<<NWIN, 256>>>(x, cw0, cb0, cw1, cb1, cw2, cb2);

    // embed: t = tf32( relu(feat @ ew + eb) + pe )
    gemm_mma<<<dim3(DM/128, NWIN/128), 256, GSMEM>>>(p_feat, p_bte, eb, p_pe, p_t, FEATD, DM, 3);

    for (int i = 0; i < 4; i++) {
        gemm_mma_qkv<<<dim3(9, NWIN/128), 256, GSMEM>>>(
            p_t,
            p_btq + (size_t)i*DM*DM, p_btk + (size_t)i*DM*DM, p_btv + (size_t)i*DM*DM,
            bq + i*DM, bk + i*DM, bv + i*DM,
            p_q, p_k, p_v);

        attn_kernel<<<dim3(NB, HH), 128, attn_smem>>>(p_q, p_k, p_v, p_ao);

        gemm_mma<<<dim3(DM/128, NWIN/128), 256, GSMEM>>>(
            p_ao, p_bto + (size_t)i*DM*DM, bo + i*DM, p_t, p_buf, DM, DM, 2);
        ln_kernel<<<NWIN, 128>>>(p_buf, g1 + i*DM, be1 + i*DM, p_t);

        gemm_mma<<<dim3(DFF/128, NWIN/128), 256, GSMEM>>>(
            p_t, p_bt1 + (size_t)i*DFF*DM, b1 + i*DFF, nullptr, p_mid, DM, DFF, 1);
        gemm_mma<<<dim3(DM/128, NWIN/128), 256, GSMEM>>>(
            p_mid, p_bt2 + (size_t)i*DM*DFF, b2 + i*DM, p_t, p_buf, DFF, DM, 2);
        ln_kernel<<<NWIN, 128>>>(p_buf, g2 + i*DM, be2 + i*DM, p_t);
    }

    cls_kernel<<<NB, 384>>>(p_t, clw, clb, out);
}

// round 5
// speedup vs baseline: 3.5047x; 1.0810x over previous
#include <cuda_runtime.h>
#include <math.h>
#include <stdint.h>

// ---------------- problem constants ----------------
#define NB    64
#define LW    128
#define DM    384
#define HH    8
#define DFF   1536
#define NWIN  (NB*LW)     // 8192
#define FEATD 2048

// ---------------- scratch (device globals, alloc-free) ----------------
__device__ float d_feat[NWIN*FEATD];
__device__ float d_t  [NWIN*DM];
__device__ float d_q  [NWIN*DM];
__device__ float d_k  [NWIN*DM];
__device__ float d_v  [NWIN*DM];
__device__ float d_ao [NWIN*DM];
__device__ float d_buf[NWIN*DM];
__device__ float d_mid[NWIN*DFF];
__device__ float d_pe [LW*DM];
__device__ float d_bt_embed[DM*FEATD];
__device__ float d_btq[4][DM*DM];
__device__ float d_btk[4][DM*DM];
__device__ float d_btv[4][DM*DM];
__device__ float d_bto[4][DM*DM];
__device__ float d_bt1[4][DFF*DM];
__device__ float d_bt2[4][DM*DFF];

// ---------------- helpers ----------------
__device__ __forceinline__ uint32_t smem_u32(const void* p) {
    uint32_t a;
    asm("{ .reg .u64 t; cvta.to.shared.u64 t, %1; cvt.u32.u64 %0, t; }" : "=r"(a) : "l"(p));
    return a;
}
__device__ __forceinline__ uint32_t tf32_bits(float x) {
    uint32_t u; asm("cvt.rna.tf32.f32 %0, %1;" : "=r"(u) : "f"(x)); return u;
}
__device__ __forceinline__ float tf32r(float x) { return __uint_as_float(tf32_bits(x)); }

__device__ __forceinline__ void cp16(uint32_t s, const void* g) {
    asm volatile("cp.async.cg.shared.global [%0], [%1], 16;" :: "r"(s), "l"(g));
}
__device__ __forceinline__ void cp_commit() { asm volatile("cp.async.commit_group;"); }
template<int N> __device__ __forceinline__ void cp_wait() {
    asm volatile("cp.async.wait_group %0;" :: "n"(N));
}
__device__ __forceinline__ void ldsm4(uint32_t* r, uint32_t addr) {
    asm volatile("ldmatrix.sync.aligned.m8n8.x4.shared.b16 {%0,%1,%2,%3}, [%4];"
        : "=r"(r[0]), "=r"(r[1]), "=r"(r[2]), "=r"(r[3]) : "r"(addr));
}
__device__ __forceinline__ void mma8(float* c, const uint32_t* a, const uint32_t* b) {
    asm volatile("mma.sync.aligned.m16n8k8.row.col.f32.tf32.tf32.f32 "
        "{%0,%1,%2,%3}, {%4,%5,%6,%7}, {%8,%9}, {%0,%1,%2,%3};"
        : "+f"(c[0]), "+f"(c[1]), "+f"(c[2]), "+f"(c[3])
        : "r"(a[0]), "r"(a[1]), "r"(a[2]), "r"(a[3]), "r"(b[0]), "r"(b[1]));
}

// SMEM geometry: per stage, A tile [128][36] + B tile [128][36] floats (rows padded 32->36)
#define ROWB   144            // 36 floats * 4B
#define TILEB  18432          // 128 * 144
#define STAGEB 36864          // A + B
#define GSMEM  (2*STAGEB)     // 73728

// ---------------- mma.sync TF32 GEMM core: C tile 128x128, K chunks of 32 ----------------
// single barrier per chunk; prefetch(kc+1) issued after the barrier (its slot's readers
// all passed the previous iteration's compute before this barrier) and overlaps compute(kc)
// epi: 0=+bias ; 1=relu(+bias) ; 2=+bias+extra[m*ldc+c] ; 3=relu(+bias)+pe[(m&127)*ldc+c]
__device__ __forceinline__ void gemm_core(
    const float* __restrict__ A, const float* __restrict__ BtBlk,
    const float* __restrict__ bias, const float* __restrict__ extra,
    float* __restrict__ C, int K, int ldc, int epi, int row0, int col0)
{
    extern __shared__ float sm[];
    uint32_t sbase = smem_u32(sm);
    int tid = threadIdx.x;

    int crow = tid >> 3, ccol4 = tid & 7;
    const float* Ag = A + (size_t)(row0 + crow) * K + ccol4 * 4;
    const float* Bg = BtBlk + (size_t)crow * K + ccol4 * 4;
    uint32_t sA = sbase + crow * ROWB + ccol4 * 16;
    uint32_t sB = sA + TILEB;
    int nk = K >> 5;

    // prologue: chunk 0 -> slot 0
    #pragma unroll
    for (int i = 0; i < 4; i++) {
        cp16(sA + i * 32 * ROWB, Ag + (size_t)(i * 32) * K);
        cp16(sB + i * 32 * ROWB, Bg + (size_t)(i * 32) * K);
    }
    cp_commit();

    int lane = tid & 31, w = tid >> 5, wm = w & 1, wn = w >> 1;
    int g = lane >> 3, lr = lane & 7;
    uint32_t aoff = sbase + ((wm * 64 + (g & 1) * 8 + lr) * 36 + (g >> 1) * 4) * 4;
    uint32_t boff = sbase + TILEB + ((wn * 32 + (g >> 1) * 8 + lr) * 36 + (g & 1) * 4) * 4;

    float c[4][4][4];
    #pragma unroll
    for (int i = 0; i < 4; i++)
        #pragma unroll
        for (int j = 0; j < 4; j++)
            #pragma unroll
            for (int q = 0; q < 4; q++) c[i][j][q] = 0.f;

    for (int kc = 0; kc < nk; kc++) {
        cp_wait<0>();
        __syncthreads();
        if (kc + 1 < nk) {
            uint32_t off = ((kc + 1) & 1) * STAGEB;
            const float* ag = Ag + (size_t)(kc + 1) * 32;
            const float* bg = Bg + (size_t)(kc + 1) * 32;
            #pragma unroll
            for (int i = 0; i < 4; i++) {
                cp16(sA + off + i * 32 * ROWB, ag + (size_t)(i * 32) * K);
                cp16(sB + off + i * 32 * ROWB, bg + (size_t)(i * 32) * K);
            }
            cp_commit();
        }
        uint32_t st = (kc & 1) * STAGEB;
        uint32_t ab = aoff + st;
        uint32_t bb = boff + st;
        #pragma unroll
        for (int ks = 0; ks < 4; ks++) {
            uint32_t af[4][4], bf[2][4];
            #pragma unroll
            for (int mf = 0; mf < 4; mf++)
                ldsm4(af[mf], ab + mf * 16 * ROWB + ks * 32);
            #pragma unroll
            for (int np = 0; np < 2; np++)
                ldsm4(bf[np], bb + np * 16 * ROWB + ks * 32);
            #pragma unroll
            for (int mf = 0; mf < 4; mf++)
                #pragma unroll
                for (int nf = 0; nf < 4; nf++)
                    mma8(c[mf][nf], af[mf], &bf[nf >> 1][(nf & 1) * 2]);
        }
    }

    // epilogue (tf32-rna rounded outputs)
    #pragma unroll
    for (int mf = 0; mf < 4; mf++) {
        #pragma unroll
        for (int half = 0; half < 2; half++) {
            int r = row0 + wm * 64 + mf * 16 + (lane >> 2) + half * 8;
            float* crow = C + (size_t)r * ldc;
            const float* exrow = nullptr;
            if (epi == 2)      exrow = extra + (size_t)r * ldc;
            else if (epi == 3) exrow = extra + (size_t)(r & (LW - 1)) * ldc;
            #pragma unroll
            for (int nf = 0; nf < 4; nf++) {
                int col = col0 + wn * 32 + nf * 8 + (lane & 3) * 2;
                float v0 = c[mf][nf][half * 2 + 0] + bias[col];
                float v1 = c[mf][nf][half * 2 + 1] + bias[col + 1];
                if (epi == 1) { v0 = fmaxf(v0, 0.f); v1 = fmaxf(v1, 0.f); }
                else if (epi == 2) { v0 += exrow[col]; v1 += exrow[col + 1]; }
                else if (epi == 3) {
                    v0 = fmaxf(v0, 0.f) + exrow[col];
                    v1 = fmaxf(v1, 0.f) + exrow[col + 1];
                }
                float2 o = make_float2(tf32r(v0), tf32r(v1));
                *(float2*)(crow + col) = o;
            }
        }
    }
}

__global__ __launch_bounds__(256, 2) void gemm_mma(
    const float* __restrict__ A, const float* __restrict__ Bt,
    const float* __restrict__ bias, const float* __restrict__ extra,
    float* __restrict__ C, int K, int N, int epi)
{
    gemm_core(A, Bt + (size_t)blockIdx.x * 128 * K, bias, extra, C, K, N, epi,
              blockIdx.y * 128, blockIdx.x * 128);
}

__global__ __launch_bounds__(256, 2) void gemm_mma_qkv(
    const float* __restrict__ A,
    const float* __restrict__ btq, const float* __restrict__ btk, const float* __restrict__ btv,
    const float* __restrict__ bqv, const float* __restrict__ bkv, const float* __restrict__ bvv,
    float* __restrict__ q, float* __restrict__ k, float* __restrict__ v)
{
    int sel = blockIdx.x / 3, j = blockIdx.x % 3;
    const float* Bt   = sel == 0 ? btq : (sel == 1 ? btk : btv);
    const float* bias = sel == 0 ? bqv : (sel == 1 ? bkv : bvv);
    float*       C    = sel == 0 ? q   : (sel == 1 ? k   : v);
    gemm_core(A, Bt + (size_t)j * 128 * DM, bias, nullptr, C, DM, DM, 0,
              blockIdx.y * 128, j * 128);
}

// ---------------- batched weight transpose with tf32-rna rounding ----------------
// out[z][n][k] = tf32(in[z][k][n]) ; z = blockIdx.z
__global__ void transpose_tf32(const float* __restrict__ in, float* __restrict__ out, int Kd, int Nd)
{
    size_t mstride = (size_t)Kd * Nd;
    in  += blockIdx.z * mstride;
    out += blockIdx.z * mstride;
    __shared__ float tile[32][33];
    int kb = blockIdx.x * 32, nb = blockIdx.y * 32;
    int tx = threadIdx.x, ty = threadIdx.y;
    #pragma unroll
    for (int j = 0; j < 32; j += 8)
        tile[ty + j][tx] = in[(size_t)(kb + ty + j) * Nd + nb + tx];
    __syncthreads();
    #pragma unroll
    for (int j = 0; j < 32; j += 8)
        out[(size_t)(nb + ty + j) * Kd + kb + tx] = tf32r(tile[tx][ty + j]);
}

// ---------------- positional encoding ----------------
__global__ void pe_kernel() {
    int idx = blockIdx.x * blockDim.x + threadIdx.x;
    if (idx >= LW * (DM / 2)) return;
    int l = idx / (DM / 2);
    int i = idx % (DM / 2);
    double ang = (double)l / pow(10000.0, (2.0 * i) / (double)DM);
    d_pe[l * DM + 2 * i]     = (float)sin(ang);
    d_pe[l * DM + 2 * i + 1] = (float)cos(ang);
}

// ---------------- fused CNN window encoder: one block per window ----------------
__global__ __launch_bounds__(256) void cnn_kernel(
    const float* __restrict__ x,
    const float* __restrict__ w0, const float* __restrict__ b0,
    const float* __restrict__ w1, const float* __restrict__ b1,
    const float* __restrict__ w2, const float* __restrict__ b2)
{
    __shared__ float sx[256];
    __shared__ float a0[4 * 128];
    __shared__ float a1[16 * 64];
    __shared__ float sw0[28];
    __shared__ float sw1[448];
    __shared__ float sw2t[112 * 64];     // [ci*7+k][c] transposed
    __shared__ float sb0[4], sb1[16], sb2[64];

    int win = blockIdx.x;
    int tid = threadIdx.x;

    sx[tid] = x[win * 256 + tid];
    if (tid < 28) sw0[tid] = w0[tid];
    if (tid < 4)  sb0[tid] = b0[tid];
    for (int i = tid; i < 448; i += 256) sw1[i] = w1[i];
    if (tid < 16) sb1[tid] = b1[tid];
    for (int i = tid; i < 7168; i += 256) {
        int c = i / 112, r = i % 112;
        sw2t[r * 64 + c] = w2[i];
    }
    if (tid < 64) sb2[tid] = b2[tid];
    __syncthreads();

    // stage 0: conv(1->4,k7,p3)+relu+pool2 : 256 -> 4x128
    for (int it = tid; it < 4 * 128; it += 256) {
        int c = it >> 7, p = it & 127;
        float acc0 = sb0[c], acc1 = sb0[c];
        #pragma unroll
        for (int k = 0; k < 7; k++) {
            float wv = sw0[c * 7 + k];
            int i0 = 2 * p + k - 3, i1 = i0 + 1;
            if (i0 >= 0 && i0 < 256) acc0 += sx[i0] * wv;
            if (i1 >= 0 && i1 < 256) acc1 += sx[i1] * wv;
        }
        a0[c * 128 + p] = fmaxf(fmaxf(acc0, acc1), 0.f);
    }
    __syncthreads();

    // stage 1: conv(4->16)+relu+pool : 4x128 -> 16x64
    for (int it = tid; it < 16 * 64; it += 256) {
        int c = it >> 6, p = it & 63;
        float acc0 = sb1[c], acc1 = sb1[c];
        for (int ci = 0; ci < 4; ci++) {
            const float* wrow = &sw1[(c * 4 + ci) * 7];
            const float* arow = &a0[ci * 128];
            #pragma unroll
            for (int k = 0; k < 7; k++) {
                float wv = wrow[k];
                int i0 = 2 * p + k - 3, i1 = i0 + 1;
                if (i0 >= 0 && i0 < 128) acc0 += arow[i0] * wv;
                if (i1 >= 0 && i1 < 128) acc1 += arow[i1] * wv;
            }
        }
        a1[c * 64 + p] = fmaxf(fmaxf(acc0, acc1), 0.f);
    }
    __syncthreads();

    // stage 2: conv(16->64)+relu+pool : 16x64 -> 64x32, register-blocked
    {
        int c = tid & 63, g = tid >> 6;
        float acc0[8], acc1[8];
        #pragma unroll
        for (int p = 0; p < 8; p++) { acc0[p] = sb2[c]; acc1[p] = sb2[c]; }
        int base = 16 * g - 3;
        for (int ci = 0; ci < 16; ci++) {
            float xin[22];
            #pragma unroll
            for (int j = 0; j < 22; j++) {
                int idx = base + j;
                xin[j] = (idx >= 0 && idx < 64) ? a1[ci * 64 + idx] : 0.f;
            }
            float wv[7];
            #pragma unroll
            for (int k = 0; k < 7; k++) wv[k] = sw2t[(ci * 7 + k) * 64 + c];
            #pragma unroll
            for (int p = 0; p < 8; p++) {
                #pragma unroll
                for (int k = 0; k < 7; k++) {
                    acc0[p] += wv[k] * xin[2 * p + k];
                    acc1[p] += wv[k] * xin[2 * p + k + 1];
                }
            }
        }
        float o[8];
        #pragma unroll
        for (int p = 0; p < 8; p++) o[p] = tf32r(fmaxf(fmaxf(acc0[p], acc1[p]), 0.f));
        float* dst = &d_feat[(size_t)win * 2048 + c * 32 + g * 8];
        *(float4*)(dst)     = *(const float4*)(o);
        *(float4*)(dst + 4) = *(const float4*)(o + 4);
    }
}

// ---------------- flash-style attention: one block per (n,h), online softmax over 32-key chunks ----------------
__global__ __launch_bounds__(128) void attn_kernel(
    const float* __restrict__ q, const float* __restrict__ k,
    const float* __restrict__ v, float* __restrict__ o)
{
    __shared__ float Ks[2][32 * 48];
    __shared__ float Vs[2][32 * 48];

    int n = blockIdx.x, h = blockIdx.y;
    int tid = threadIdx.x;

    float4 qr[12];
    {
        const float4* qp = (const float4*)(q + (size_t)(n * 128 + tid) * DM + h * 48);
        #pragma unroll
        for (int j = 0; j < 12; j++) qr[j] = qp[j];
    }

    // loader: chunk c (keys c*32..c*32+31) into buffer b; 384 float4 per tile, 3 per thread
    int ls = tid / 12 * 0;  (void)ls;
    #define ATTN_ISSUE(c, b)                                                            \
        {                                                                               \
            _Pragma("unroll")                                                           \
            for (int f = tid; f < 384; f += 128) {                                      \
                int s = f / 12, j = f % 12;                                             \
                size_t gg = (size_t)(n * 128 + (c) * 32 + s) * DM + h * 48 + j * 4;     \
                cp16(smem_u32(&Ks[b][s * 48 + j * 4]), kk + gg);                        \
                cp16(smem_u32(&Vs[b][s * 48 + j * 4]), vv + gg);                        \
            }                                                                           \
            cp_commit();                                                                \
        }
    const float* kk = k;
    const float* vv = v;

    ATTN_ISSUE(0, 0);

    const float temp = 0.14433756729740643f;   // 1/sqrt(48)
    float m = -1e30f, ssum = 0.f;
    float4 acc[12];
    #pragma unroll
    for (int j = 0; j < 12; j++) acc[j] = make_float4(0.f, 0.f, 0.f, 0.f);

    for (int c = 0; c < 4; c++) {
        cp_wait<0>();
        __syncthreads();
        if (c < 3) ATTN_ISSUE(c + 1, (c + 1) & 1);
        int b = c & 1;

        float sc[32];
        float cm = -1e30f;
        #pragma unroll 4
        for (int s = 0; s < 32; s++) {
            const float4* kr = (const float4*)&Ks[b][s * 48];
            float d = 0.f;
            #pragma unroll
            for (int j = 0; j < 12; j++) {
                float4 a = qr[j], bb2 = kr[j];
                d += a.x * bb2.x + a.y * bb2.y + a.z * bb2.z + a.w * bb2.w;
            }
            d *= temp;
            sc[s] = d;
            cm = fmaxf(cm, d);
        }
        float nm = fmaxf(m, cm);
        float f = __expf(m - nm);
        ssum *= f;
        #pragma unroll
        for (int j = 0; j < 12; j++) {
            acc[j].x *= f; acc[j].y *= f; acc[j].z *= f; acc[j].w *= f;
        }
        #pragma unroll 4
        for (int s = 0; s < 32; s++) {
            float p = __expf(sc[s] - nm);
            ssum += p;
            const float4* vr = (const float4*)&Vs[b][s * 48];
            #pragma unroll
            for (int j = 0; j < 12; j++) {
                float4 bb2 = vr[j];
                acc[j].x += p * bb2.x; acc[j].y += p * bb2.y;
                acc[j].z += p * bb2.z; acc[j].w += p * bb2.w;
            }
        }
        m = nm;
    }

    float inv = 1.0f / ssum;
    float4* op = (float4*)(o + (size_t)(n * 128 + tid) * DM + h * 48);
    #pragma unroll
    for (int j = 0; j < 12; j++)
        op[j] = make_float4(tf32r(acc[j].x * inv), tf32r(acc[j].y * inv),
                            tf32r(acc[j].z * inv), tf32r(acc[j].w * inv));
}

// ---------------- layernorm (384), one block per row ----------------
__global__ __launch_bounds__(128) void ln_kernel(
    const float* __restrict__ in, const float* __restrict__ g,
    const float* __restrict__ b, float* __restrict__ out)
{
    __shared__ float red[128];
    int r = blockIdx.x, tid = threadIdx.x;
    const float* row = in + (size_t)r * DM;
    float v0 = row[tid], v1 = row[tid + 128], v2 = row[tid + 256];

    red[tid] = v0 + v1 + v2;
    __syncthreads();
    for (int st = 64; st > 0; st >>= 1) { if (tid < st) red[tid] += red[tid + st]; __syncthreads(); }
    float mean = red[0] * (1.0f / 384.0f);
    __syncthreads();

    float d0 = v0 - mean, d1 = v1 - mean, d2 = v2 - mean;
    red[tid] = d0 * d0 + d1 * d1 + d2 * d2;
    __syncthreads();
    for (int st = 64; st > 0; st >>= 1) { if (tid < st) red[tid] += red[tid + st]; __syncthreads(); }
    float inv = rsqrtf(red[0] * (1.0f / 384.0f) + 1e-5f);

    float* orow = out + (size_t)r * DM;
    orow[tid]       = tf32r(d0 * inv * g[tid]       + b[tid]);
    orow[tid + 128] = tf32r(d1 * inv * g[tid + 128] + b[tid + 128]);
    orow[tid + 256] = tf32r(d2 * inv * g[tid + 256] + b[tid + 256]);
}

// ---------------- mean-pool over L + classifier ----------------
__global__ __launch_bounds__(384) void cls_kernel(
    const float* __restrict__ t, const float* __restrict__ w,
    const float* __restrict__ b, float* __restrict__ out)
{
    __shared__ float red[384];
    int n = blockIdx.x, d = threadIdx.x;
    float s = 0.f;
    for (int l = 0; l < 128; l++) s += t[(size_t)(n * 128 + l) * DM + d];
    red[d] = (s * (1.0f / 128.0f)) * w[d];
    __syncthreads();
    if (d < 128) red[d] += red[d + 128] + red[d + 256];
    __syncthreads();
    for (int st = 64; st > 0; st >>= 1) { if (d < st) red[d] += red[d + st]; __syncthreads(); }
    if (d == 0) out[n] = red[0] + b[0];
}

// ---------------- launcher ----------------
extern "C" void kernel_launch(void* const* d_in, const int* in_sizes, int n_in,
                              void* d_out, int out_size)
{
    const float* x   = (const float*)d_in[0];
    const float* cw0 = (const float*)d_in[1];
    const float* cb0 = (const float*)d_in[2];
    const float* cw1 = (const float*)d_in[3];
    const float* cb1 = (const float*)d_in[4];
    const float* cw2 = (const float*)d_in[5];
    const float* cb2 = (const float*)d_in[6];
    const float* ew  = (const float*)d_in[7];
    const float* eb  = (const float*)d_in[8];

    const float *Wq,*Wk,*Wv,*Wo,*W1,*W2,*bq,*bk,*bv,*bo,*b1,*b2;
    if (in_sizes[10] == 1536) {
        Wq=(const float*)d_in[9];  bq=(const float*)d_in[10];
        Wk=(const float*)d_in[11]; bk=(const float*)d_in[12];
        Wv=(const float*)d_in[13]; bv=(const float*)d_in[14];
        Wo=(const float*)d_in[15]; bo=(const float*)d_in[16];
        W1=(const float*)d_in[17]; b1=(const float*)d_in[18];
        W2=(const float*)d_in[19]; b2=(const float*)d_in[20];
    } else {
        Wq=(const float*)d_in[9];  Wk=(const float*)d_in[10];
        Wv=(const float*)d_in[11]; Wo=(const float*)d_in[12];
        W1=(const float*)d_in[13]; W2=(const float*)d_in[14];
        bq=(const float*)d_in[15]; bk=(const float*)d_in[16];
        bv=(const float*)d_in[17]; bo=(const float*)d_in[18];
        b1=(const float*)d_in[19]; b2=(const float*)d_in[20];
    }
    const float* g1  = (const float*)d_in[21];
    const float* be1 = (const float*)d_in[22];
    const float* g2  = (const float*)d_in[23];
    const float* be2 = (const float*)d_in[24];
    const float* clw = (const float*)d_in[25];
    const float* clb = (const float*)d_in[26];
    float* out = (float*)d_out;

    float *p_feat,*p_t,*p_q,*p_k,*p_v,*p_ao,*p_buf,*p_mid,*p_pe;
    float *p_bte,*p_btq,*p_btk,*p_btv,*p_bto,*p_bt1,*p_bt2;
    cudaGetSymbolAddress((void**)&p_feat, d_feat);
    cudaGetSymbolAddress((void**)&p_t,   d_t);
    cudaGetSymbolAddress((void**)&p_q,   d_q);
    cudaGetSymbolAddress((void**)&p_k,   d_k);
    cudaGetSymbolAddress((void**)&p_v,   d_v);
    cudaGetSymbolAddress((void**)&p_ao,  d_ao);
    cudaGetSymbolAddress((void**)&p_buf, d_buf);
    cudaGetSymbolAddress((void**)&p_mid, d_mid);
    cudaGetSymbolAddress((void**)&p_pe,  d_pe);
    cudaGetSymbolAddress((void**)&p_bte, d_bt_embed);
    cudaGetSymbolAddress((void**)&p_btq, d_btq);
    cudaGetSymbolAddress((void**)&p_btk, d_btk);
    cudaGetSymbolAddress((void**)&p_btv, d_btv);
    cudaGetSymbolAddress((void**)&p_bto, d_bto);
    cudaGetSymbolAddress((void**)&p_bt1, d_bt1);
    cudaGetSymbolAddress((void**)&p_bt2, d_bt2);

    cudaFuncSetAttribute(gemm_mma,     cudaFuncAttributeMaxDynamicSharedMemorySize, GSMEM);
    cudaFuncSetAttribute(gemm_mma_qkv, cudaFuncAttributeMaxDynamicSharedMemorySize, GSMEM);

    dim3 tb(32, 8);
    // batched weight transposes (tf32-rna): 7 launches total
    transpose_tf32<<<dim3(FEATD/32, DM/32, 1), tb>>>(ew, p_bte, FEATD, DM);
    transpose_tf32<<<dim3(DM/32, DM/32, 4), tb>>>(Wq, p_btq, DM, DM);
    transpose_tf32<<<dim3(DM/32, DM/32, 4), tb>>>(Wk, p_btk, DM, DM);
    transpose_tf32<<<dim3(DM/32, DM/32, 4), tb>>>(Wv, p_btv, DM, DM);
    transpose_tf32<<<dim3(DM/32, DM/32, 4), tb>>>(Wo, p_bto, DM, DM);
    transpose_tf32<<<dim3(DM/32, DFF/32, 4), tb>>>(W1, p_bt1, DM, DFF);
    transpose_tf32<<<dim3(DFF/32, DM/32, 4), tb>>>(W2, p_bt2, DFF, DM);

    pe_kernel<<<(LW*(DM/2) + 255)/256, 256>>>();
    cnn_kernel<<<NWIN, 256>>>(x, cw0, cb0, cw1, cb1, cw2, cb2);

    // embed: t = tf32( relu(feat @ ew + eb) + pe )
    gemm_mma<<<dim3(DM/128, NWIN/128), 256, GSMEM>>>(p_feat, p_bte, eb, p_pe, p_t, FEATD, DM, 3);

    for (int i = 0; i < 4; i++) {
        gemm_mma_qkv<<<dim3(9, NWIN/128), 256, GSMEM>>>(
            p_t,
            p_btq + (size_t)i*DM*DM, p_btk + (size_t)i*DM*DM, p_btv + (size_t)i*DM*DM,
            bq + i*DM, bk + i*DM, bv + i*DM,
            p_q, p_k, p_v);

        attn_kernel<<<dim3(NB, HH), 128>>>(p_q, p_k, p_v, p_ao);

        gemm_mma<<<dim3(DM/128, NWIN/128), 256, GSMEM>>>(
            p_ao, p_bto + (size_t)i*DM*DM, bo + i*DM, p_t, p_buf, DM, DM, 2);
        ln_kernel<<<NWIN, 128>>>(p_buf, g1 + i*DM, be1 + i*DM, p_t);

        gemm_mma<<<dim3(DFF/128, NWIN/128), 256, GSMEM>>>(
            p_t, p_bt1 + (size_t)i*DFF*DM, b1 + i*DFF, nullptr, p_mid, DM, DFF, 1);
        gemm_mma<<<dim3(DM/128, NWIN/128), 256, GSMEM>>>(
            p_mid, p_bt2 + (size_t)i*DM*DFF, b2 + i*DM, p_t, p_buf, DFF, DM, 2);
        ln_kernel<<<NWIN, 128>>>(p_buf, g2 + i*DM, be2 + i*DM, p_t);
    }

    cls_kernel<<<NB, 384>>>(p_t, clw, clb, out);
}

// round 8
// speedup vs baseline: 3.6941x; 1.0540x over previous
#include <cuda_runtime.h>
#include <math.h>
#include <stdint.h>

// ---------------- problem constants ----------------
#define NB    64
#define LW    128
#define DM    384
#define HH    8
#define DFF   1536
#define NWIN  (NB*LW)     // 8192
#define FEATD 2048

// ---------------- scratch (device globals, alloc-free) ----------------
__device__ float d_feat[NWIN*FEATD];
__device__ float d_t  [NWIN*DM];
__device__ float d_q  [NWIN*DM];
__device__ float d_k  [NWIN*DM];
__device__ float d_v  [NWIN*DM];
__device__ float d_ao [NWIN*DM];
__device__ float d_buf[NWIN*DM];
__device__ float d_mid[NWIN*DFF];
__device__ float d_pe [LW*DM];
__device__ float d_bt_embed[DM*FEATD];
__device__ float d_btq[4][DM*DM];
__device__ float d_btk[4][DM*DM];
__device__ float d_btv[4][DM*DM];
__device__ float d_bto[4][DM*DM];
__device__ float d_bt1[4][DFF*DM];
__device__ float d_bt2[4][DM*DFF];

// ---------------- helpers ----------------
__device__ __forceinline__ uint32_t smem_u32(const void* p) {
    uint32_t a;
    asm("{ .reg .u64 t; cvta.to.shared.u64 t, %1; cvt.u32.u64 %0, t; }" : "=r"(a) : "l"(p));
    return a;
}
__device__ __forceinline__ uint32_t tf32_bits(float x) {
    uint32_t u; asm("cvt.rna.tf32.f32 %0, %1;" : "=r"(u) : "f"(x)); return u;
}
__device__ __forceinline__ float tf32r(float x) { return __uint_as_float(tf32_bits(x)); }

__device__ __forceinline__ void cp16(uint32_t s, const void* g) {
    asm volatile("cp.async.cg.shared.global [%0], [%1], 16;" :: "r"(s), "l"(g));
}
__device__ __forceinline__ void cp_commit() { asm volatile("cp.async.commit_group;"); }
template<int N> __device__ __forceinline__ void cp_wait() {
    asm volatile("cp.async.wait_group %0;" :: "n"(N));
}
__device__ __forceinline__ void ldsm4(uint32_t* r, uint32_t addr) {
    asm volatile("ldmatrix.sync.aligned.m8n8.x4.shared.b16 {%0,%1,%2,%3}, [%4];"
        : "=r"(r[0]), "=r"(r[1]), "=r"(r[2]), "=r"(r[3]) : "r"(addr));
}
__device__ __forceinline__ void mma8(float* c, const uint32_t* a, const uint32_t* b) {
    asm volatile("mma.sync.aligned.m16n8k8.row.col.f32.tf32.tf32.f32 "
        "{%0,%1,%2,%3}, {%4,%5,%6,%7}, {%8,%9}, {%0,%1,%2,%3};"
        : "+f"(c[0]), "+f"(c[1]), "+f"(c[2]), "+f"(c[3])
        : "r"(a[0]), "r"(a[1]), "r"(a[2]), "r"(a[3]), "r"(b[0]), "r"(b[1]));
}

// SMEM geometry per stage: A tile [64][36] + B tile [128][36] floats (rows padded 32->36)
#define ROWB    144            // 36 floats * 4B
#define ATILEB  9216           // 64 * 144
#define BTILEB  18432          // 128 * 144
#define STAGEB  27648          // A + B
#define GSMEM   (2*STAGEB)     // 55296

// ---------------- mma.sync TF32 GEMM core: C tile 64x128, K chunks of 32 ----------------
// single barrier per chunk; prefetch(kc+1) issued post-barrier, overlaps compute(kc)
// epi: 0=+bias ; 1=relu(+bias) ; 2=+bias+extra[m*ldc+c] ; 3=relu(+bias)+pe[(m&127)*ldc+c]
__device__ __forceinline__ void gemm_core(
    const float* __restrict__ A, const float* __restrict__ BtBlk,
    const float* __restrict__ bias, const float* __restrict__ extra,
    float* __restrict__ C, int K, int ldc, int epi, int row0, int col0)
{
    extern __shared__ float sm[];
    uint32_t sbase = smem_u32(sm);
    int tid = threadIdx.x;

    // load geometry: A 64x32 = 512 float4 (2/thread), B 128x32 = 1024 float4 (4/thread)
    int lrow = tid >> 3, lc4 = tid & 7;
    const float* Ag = A + (size_t)(row0 + lrow) * K + lc4 * 4;
    const float* Bg = BtBlk + (size_t)lrow * K + lc4 * 4;
    uint32_t sA = sbase + lrow * ROWB + lc4 * 16;
    uint32_t sB = sbase + ATILEB + lrow * ROWB + lc4 * 16;
    int nk = K >> 5;

    // prologue: chunk 0 -> slot 0
    #pragma unroll
    for (int i = 0; i < 2; i++)
        cp16(sA + i * 32 * ROWB, Ag + (size_t)(i * 32) * K);
    #pragma unroll
    for (int i = 0; i < 4; i++)
        cp16(sB + i * 32 * ROWB, Bg + (size_t)(i * 32) * K);
    cp_commit();

    int lane = tid & 31, w = tid >> 5, wm = w & 1, wn = w >> 1;
    int g = lane >> 3, lr = lane & 7;
    uint32_t aoff = sbase + ((wm * 32 + (g & 1) * 8 + lr) * 36 + (g >> 1) * 4) * 4;
    uint32_t boff = sbase + ATILEB + ((wn * 32 + (g >> 1) * 8 + lr) * 36 + (g & 1) * 4) * 4;

    float c[2][4][4];
    #pragma unroll
    for (int i = 0; i < 2; i++)
        #pragma unroll
        for (int j = 0; j < 4; j++)
            #pragma unroll
            for (int q = 0; q < 4; q++) c[i][j][q] = 0.f;

    for (int kc = 0; kc < nk; kc++) {
        cp_wait<0>();
        __syncthreads();
        if (kc + 1 < nk) {
            uint32_t off = ((kc + 1) & 1) * STAGEB;
            const float* ag = Ag + (size_t)(kc + 1) * 32;
            const float* bg = Bg + (size_t)(kc + 1) * 32;
            #pragma unroll
            for (int i = 0; i < 2; i++)
                cp16(sA + off + i * 32 * ROWB, ag + (size_t)(i * 32) * K);
            #pragma unroll
            for (int i = 0; i < 4; i++)
                cp16(sB + off + i * 32 * ROWB, bg + (size_t)(i * 32) * K);
            cp_commit();
        }
        uint32_t st = (kc & 1) * STAGEB;
        uint32_t ab = aoff + st;
        uint32_t bb = boff + st;
        #pragma unroll
        for (int ks = 0; ks < 4; ks++) {
            uint32_t af[2][4], bf[2][4];
            #pragma unroll
            for (int mf = 0; mf < 2; mf++)
                ldsm4(af[mf], ab + mf * 16 * ROWB + ks * 32);
            #pragma unroll
            for (int np = 0; np < 2; np++)
                ldsm4(bf[np], bb + np * 16 * ROWB + ks * 32);
            #pragma unroll
            for (int mf = 0; mf < 2; mf++)
                #pragma unroll
                for (int nf = 0; nf < 4; nf++)
                    mma8(c[mf][nf], af[mf], &bf[nf >> 1][(nf & 1) * 2]);
        }
    }

    // epilogue (tf32-rna rounded outputs)
    #pragma unroll
    for (int mf = 0; mf < 2; mf++) {
        #pragma unroll
        for (int half = 0; half < 2; half++) {
            int r = row0 + wm * 32 + mf * 16 + (lane >> 2) + half * 8;
            float* crow = C + (size_t)r * ldc;
            const float* exrow = nullptr;
            if (epi == 2)      exrow = extra + (size_t)r * ldc;
            else if (epi == 3) exrow = extra + (size_t)(r & (LW - 1)) * ldc;
            #pragma unroll
            for (int nf = 0; nf < 4; nf++) {
                int col = col0 + wn * 32 + nf * 8 + (lane & 3) * 2;
                float v0 = c[mf][nf][half * 2 + 0] + bias[col];
                float v1 = c[mf][nf][half * 2 + 1] + bias[col + 1];
                if (epi == 1) { v0 = fmaxf(v0, 0.f); v1 = fmaxf(v1, 0.f); }
                else if (epi == 2) { v0 += exrow[col]; v1 += exrow[col + 1]; }
                else if (epi == 3) {
                    v0 = fmaxf(v0, 0.f) + exrow[col];
                    v1 = fmaxf(v1, 0.f) + exrow[col + 1];
                }
                float2 o = make_float2(tf32r(v0), tf32r(v1));
                *(float2*)(crow + col) = o;
            }
        }
    }
}

__global__ __launch_bounds__(256, 3) void gemm_mma(
    const float* __restrict__ A, const float* __restrict__ Bt,
    const float* __restrict__ bias, const float* __restrict__ extra,
    float* __restrict__ C, int K, int N, int epi)
{
    gemm_core(A, Bt + (size_t)blockIdx.x * 128 * K, bias, extra, C, K, N, epi,
              blockIdx.y * 64, blockIdx.x * 128);
}

__global__ __launch_bounds__(256, 3) void gemm_mma_qkv(
    const float* __restrict__ A,
    const float* __restrict__ btq, const float* __restrict__ btk, const float* __restrict__ btv,
    const float* __restrict__ bqv, const float* __restrict__ bkv, const float* __restrict__ bvv,
    float* __restrict__ q, float* __restrict__ k, float* __restrict__ v)
{
    int sel = blockIdx.x / 3, j = blockIdx.x % 3;
    const float* Bt   = sel == 0 ? btq : (sel == 1 ? btk : btv);
    const float* bias = sel == 0 ? bqv : (sel == 1 ? bkv : bvv);
    float*       C    = sel == 0 ? q   : (sel == 1 ? k   : v);
    gemm_core(A, Bt + (size_t)j * 128 * DM, bias, nullptr, C, DM, DM, 0,
              blockIdx.y * 64, j * 128);
}

// ---------------- batched weight transpose with tf32-rna rounding ----------------
// out[z][n][k] = tf32(in[z][k][n]) ; z = blockIdx.z
__global__ void transpose_tf32(const float* __restrict__ in, float* __restrict__ out, int Kd, int Nd)
{
    size_t mstride = (size_t)Kd * Nd;
    in  += blockIdx.z * mstride;
    out += blockIdx.z * mstride;
    __shared__ float tile[32][33];
    int kb = blockIdx.x * 32, nb = blockIdx.y * 32;
    int tx = threadIdx.x, ty = threadIdx.y;
    #pragma unroll
    for (int j = 0; j < 32; j += 8)
        tile[ty + j][tx] = in[(size_t)(kb + ty + j) * Nd + nb + tx];
    __syncthreads();
    #pragma unroll
    for (int j = 0; j < 32; j += 8)
        out[(size_t)(nb + ty + j) * Kd + kb + tx] = tf32r(tile[tx][ty + j]);
}

// merged transpose for the 16 DM x DM attention weight matrices (z = sel*4 + layer)
__global__ void transpose_tf32_qkvo(
    const float* __restrict__ Wq, const float* __restrict__ Wk,
    const float* __restrict__ Wv, const float* __restrict__ Wo,
    float* __restrict__ oq, float* __restrict__ ok,
    float* __restrict__ ov, float* __restrict__ oo)
{
    int z = blockIdx.z, sel = z >> 2, layer = z & 3;
    const float* in = (sel == 0 ? Wq : sel == 1 ? Wk : sel == 2 ? Wv : Wo)
                      + (size_t)layer * DM * DM;
    float* out = (sel == 0 ? oq : sel == 1 ? ok : sel == 2 ? ov : oo)
                 + (size_t)layer * DM * DM;
    __shared__ float tile[32][33];
    int kb = blockIdx.x * 32, nb = blockIdx.y * 32;
    int tx = threadIdx.x, ty = threadIdx.y;
    #pragma unroll
    for (int j = 0; j < 32; j += 8)
        tile[ty + j][tx] = in[(size_t)(kb + ty + j) * DM + nb + tx];
    __syncthreads();
    #pragma unroll
    for (int j = 0; j < 32; j += 8)
        out[(size_t)(nb + ty + j) * DM + kb + tx] = tf32r(tile[tx][ty + j]);
}

// ---------------- positional encoding ----------------
__global__ void pe_kernel() {
    int idx = blockIdx.x * blockDim.x + threadIdx.x;
    if (idx >= LW * (DM / 2)) return;
    int l = idx / (DM / 2);
    int i = idx % (DM / 2);
    double ang = (double)l / pow(10000.0, (2.0 * i) / (double)DM);
    d_pe[l * DM + 2 * i]     = (float)sin(ang);
    d_pe[l * DM + 2 * i + 1] = (float)cos(ang);
}

// ---------------- fused CNN window encoder: one block per window ----------------
__global__ __launch_bounds__(256) void cnn_kernel(
    const float* __restrict__ x,
    const float* __restrict__ w0, const float* __restrict__ b0,
    const float* __restrict__ w1, const float* __restrict__ b1,
    const float* __restrict__ w2, const float* __restrict__ b2)
{
    __shared__ float sx[256];
    __shared__ float a0[4 * 128];
    __shared__ float a1[16 * 64];
    __shared__ float sw0[28];
    __shared__ float sw1[448];
    __shared__ float sw2t[112 * 64];     // [ci*7+k][c] transposed
    __shared__ float sb0[4], sb1[16], sb2[64];

    int win = blockIdx.x;
    int tid = threadIdx.x;

    sx[tid] = x[win * 256 + tid];
    if (tid < 28) sw0[tid] = w0[tid];
    if (tid < 4)  sb0[tid] = b0[tid];
    for (int i = tid; i < 448; i += 256) sw1[i] = w1[i];
    if (tid < 16) sb1[tid] = b1[tid];
    for (int i = tid; i < 7168; i += 256) {
        int c = i / 112, r = i % 112;
        sw2t[r * 64 + c] = w2[i];
    }
    if (tid < 64) sb2[tid] = b2[tid];
    __syncthreads();

    // stage 0
    for (int it = tid; it < 4 * 128; it += 256) {
        int c = it >> 7, p = it & 127;
        float acc0 = sb0[c], acc1 = sb0[c];
        #pragma unroll
        for (int k = 0; k < 7; k++) {
            float wv = sw0[c * 7 + k];
            int i0 = 2 * p + k - 3, i1 = i0 + 1;
            if (i0 >= 0 && i0 < 256) acc0 += sx[i0] * wv;
            if (i1 >= 0 && i1 < 256) acc1 += sx[i1] * wv;
        }
        a0[c * 128 + p] = fmaxf(fmaxf(acc0, acc1), 0.f);
    }
    __syncthreads();

    // stage 1
    for (int it = tid; it < 16 * 64; it += 256) {
        int c = it >> 6, p = it & 63;
        float acc0 = sb1[c], acc1 = sb1[c];
        for (int ci = 0; ci < 4; ci++) {
            const float* wrow = &sw1[(c * 4 + ci) * 7];
            const float* arow = &a0[ci * 128];
            #pragma unroll
            for (int k = 0; k < 7; k++) {
                float wv = wrow[k];
                int i0 = 2 * p + k - 3, i1 = i0 + 1;
                if (i0 >= 0 && i0 < 128) acc0 += arow[i0] * wv;
                if (i1 >= 0 && i1 < 128) acc1 += arow[i1] * wv;
            }
        }
        a1[c * 64 + p] = fmaxf(fmaxf(acc0, acc1), 0.f);
    }
    __syncthreads();

    // stage 2 (register-blocked)
    {
        int c = tid & 63, g = tid >> 6;
        float acc0[8], acc1[8];
        #pragma unroll
        for (int p = 0; p < 8; p++) { acc0[p] = sb2[c]; acc1[p] = sb2[c]; }
        int base = 16 * g - 3;
        for (int ci = 0; ci < 16; ci++) {
            float xin[22];
            #pragma unroll
            for (int j = 0; j < 22; j++) {
                int idx = base + j;
                xin[j] = (idx >= 0 && idx < 64) ? a1[ci * 64 + idx] : 0.f;
            }
            float wv[7];
            #pragma unroll
            for (int k = 0; k < 7; k++) wv[k] = sw2t[(ci * 7 + k) * 64 + c];
            #pragma unroll
            for (int p = 0; p < 8; p++) {
                #pragma unroll
                for (int k = 0; k < 7; k++) {
                    acc0[p] += wv[k] * xin[2 * p + k];
                    acc1[p] += wv[k] * xin[2 * p + k + 1];
                }
            }
        }
        float o[8];
        #pragma unroll
        for (int p = 0; p < 8; p++) o[p] = tf32r(fmaxf(fmaxf(acc0[p], acc1[p]), 0.f));
        float* dst = &d_feat[(size_t)win * 2048 + c * 32 + g * 8];
        *(float4*)(dst)     = *(const float4*)(o);
        *(float4*)(dst + 4) = *(const float4*)(o + 4);
    }
}

// ---------------- flash-style attention: one block per (n,h) ----------------
__global__ __launch_bounds__(128) void attn_kernel(
    const float* __restrict__ q, const float* __restrict__ k,
    const float* __restrict__ v, float* __restrict__ o)
{
    __shared__ float Ks[2][32 * 48];
    __shared__ float Vs[2][32 * 48];

    int n = blockIdx.x, h = blockIdx.y;
    int tid = threadIdx.x;

    float4 qr[12];
    {
        const float4* qp = (const float4*)(q + (size_t)(n * 128 + tid) * DM + h * 48);
        #pragma unroll
        for (int j = 0; j < 12; j++) qr[j] = qp[j];
    }

    #define ATTN_ISSUE(c, b)                                                            \
        {                                                                               \
            _Pragma("unroll")                                                           \
            for (int f = tid; f < 384; f += 128) {                                      \
                int s = f / 12, j = f % 12;                                             \
                size_t gg = (size_t)(n * 128 + (c) * 32 + s) * DM + h * 48 + j * 4;     \
                cp16(smem_u32(&Ks[b][s * 48 + j * 4]), kk + gg);                        \
                cp16(smem_u32(&Vs[b][s * 48 + j * 4]), vv + gg);                        \
            }                                                                           \
            cp_commit();                                                                \
        }
    const float* kk = k;
    const float* vv = v;

    ATTN_ISSUE(0, 0);

    const float temp = 0.14433756729740643f;   // 1/sqrt(48)
    float m = -1e30f, ssum = 0.f;
    float4 acc[12];
    #pragma unroll
    for (int j = 0; j < 12; j++) acc[j] = make_float4(0.f, 0.f, 0.f, 0.f);

    for (int c = 0; c < 4; c++) {
        cp_wait<0>();
        __syncthreads();
        if (c < 3) ATTN_ISSUE(c + 1, (c + 1) & 1);
        int b = c & 1;

        float sc[32];
        float cm = -1e30f;
        #pragma unroll 4
        for (int s = 0; s < 32; s++) {
            const float4* kr = (const float4*)&Ks[b][s * 48];
            float d = 0.f;
            #pragma unroll
            for (int j = 0; j < 12; j++) {
                float4 a = qr[j], bb2 = kr[j];
                d += a.x * bb2.x + a.y * bb2.y + a.z * bb2.z + a.w * bb2.w;
            }
            d *= temp;
            sc[s] = d;
            cm = fmaxf(cm, d);
        }
        float nm = fmaxf(m, cm);
        float f = __expf(m - nm);
        ssum *= f;
        #pragma unroll
        for (int j = 0; j < 12; j++) {
            acc[j].x *= f; acc[j].y *= f; acc[j].z *= f; acc[j].w *= f;
        }
        #pragma unroll 4
        for (int s = 0; s < 32; s++) {
            float p = __expf(sc[s] - nm);
            ssum += p;
            const float4* vr = (const float4*)&Vs[b][s * 48];
            #pragma unroll
            for (int j = 0; j < 12; j++) {
                float4 bb2 = vr[j];
                acc[j].x += p * bb2.x; acc[j].y += p * bb2.y;
                acc[j].z += p * bb2.z; acc[j].w += p * bb2.w;
            }
        }
        m = nm;
    }

    float inv = 1.0f / ssum;
    float4* op = (float4*)(o + (size_t)(n * 128 + tid) * DM + h * 48);
    #pragma unroll
    for (int j = 0; j < 12; j++)
        op[j] = make_float4(tf32r(acc[j].x * inv), tf32r(acc[j].y * inv),
                            tf32r(acc[j].z * inv), tf32r(acc[j].w * inv));
}

// ---------------- layernorm (384): warp per row, 8 rows per block ----------------
__global__ __launch_bounds__(256) void ln_kernel(
    const float* __restrict__ in, const float* __restrict__ g,
    const float* __restrict__ b, float* __restrict__ out)
{
    int row = blockIdx.x * 8 + (threadIdx.x >> 5);
    int lane = threadIdx.x & 31;
    const float4* rp = (const float4*)(in + (size_t)row * DM);

    float4 v0 = rp[lane], v1 = rp[lane + 32], v2 = rp[lane + 64];
    float s = v0.x + v0.y + v0.z + v0.w + v1.x + v1.y + v1.z + v1.w
            + v2.x + v2.y + v2.z + v2.w;
    #pragma unroll
    for (int o2 = 16; o2; o2 >>= 1) s += __shfl_xor_sync(0xFFFFFFFFu, s, o2);
    float mean = s * (1.0f / 384.0f);

    float4 d0 = make_float4(v0.x - mean, v0.y - mean, v0.z - mean, v0.w - mean);
    float4 d1 = make_float4(v1.x - mean, v1.y - mean, v1.z - mean, v1.w - mean);
    float4 d2 = make_float4(v2.x - mean, v2.y - mean, v2.z - mean, v2.w - mean);
    float q = d0.x*d0.x + d0.y*d0.y + d0.z*d0.z + d0.w*d0.w
            + d1.x*d1.x + d1.y*d1.y + d1.z*d1.z + d1.w*d1.w
            + d2.x*d2.x + d2.y*d2.y + d2.z*d2.z + d2.w*d2.w;
    #pragma unroll
    for (int o2 = 16; o2; o2 >>= 1) q += __shfl_xor_sync(0xFFFFFFFFu, q, o2);
    float inv = rsqrtf(q * (1.0f / 384.0f) + 1e-5f);

    const float4* gp = (const float4*)g;
    const float4* bp = (const float4*)b;
    float4* op = (float4*)(out + (size_t)row * DM);
    float4 g0 = gp[lane], g1v = gp[lane + 32], g2v = gp[lane + 64];
    float4 b0 = bp[lane], b1v = bp[lane + 32], b2v = bp[lane + 64];
    op[lane]      = make_float4(tf32r(d0.x*inv*g0.x + b0.x),  tf32r(d0.y*inv*g0.y + b0.y),
                                tf32r(d0.z*inv*g0.z + b0.z),  tf32r(d0.w*inv*g0.w + b0.w));
    op[lane + 32] = make_float4(tf32r(d1.x*inv*g1v.x + b1v.x), tf32r(d1.y*inv*g1v.y + b1v.y),
                                tf32r(d1.z*inv*g1v.z + b1v.z), tf32r(d1.w*inv*g1v.w + b1v.w));
    op[lane + 64] = make_float4(tf32r(d2.x*inv*g2v.x + b2v.x), tf32r(d2.y*inv*g2v.y + b2v.y),
                                tf32r(d2.z*inv*g2v.z + b2v.z), tf32r(d2.w*inv*g2v.w + b2v.w));
}

// ---------------- mean-pool over L + classifier ----------------
__global__ __launch_bounds__(384) void cls_kernel(
    const float* __restrict__ t, const float* __restrict__ w,
    const float* __restrict__ b, float* __restrict__ out)
{
    __shared__ float red[384];
    int n = blockIdx.x, d = threadIdx.x;
    float s = 0.f;
    for (int l = 0; l < 128; l++) s += t[(size_t)(n * 128 + l) * DM + d];
    red[d] = (s * (1.0f / 128.0f)) * w[d];
    __syncthreads();
    if (d < 128) red[d] += red[d + 128] + red[d + 256];
    __syncthreads();
    for (int st = 64; st > 0; st >>= 1) { if (d < st) red[d] += red[d + st]; __syncthreads(); }
    if (d == 0) out[n] = red[0] + b[0];
}

// ---------------- launcher ----------------
extern "C" void kernel_launch(void* const* d_in, const int* in_sizes, int n_in,
                              void* d_out, int out_size)
{
    const float* x   = (const float*)d_in[0];
    const float* cw0 = (const float*)d_in[1];
    const float* cb0 = (const float*)d_in[2];
    const float* cw1 = (const float*)d_in[3];
    const float* cb1 = (const float*)d_in[4];
    const float* cw2 = (const float*)d_in[5];
    const float* cb2 = (const float*)d_in[6];
    const float* ew  = (const float*)d_in[7];
    const float* eb  = (const float*)d_in[8];

    const float *Wq,*Wk,*Wv,*Wo,*W1,*W2,*bq,*bk,*bv,*bo,*b1,*b2;
    if (in_sizes[10] == 1536) {
        Wq=(const float*)d_in[9];  bq=(const float*)d_in[10];
        Wk=(const float*)d_in[11]; bk=(const float*)d_in[12];
        Wv=(const float*)d_in[13]; bv=(const float*)d_in[14];
        Wo=(const float*)d_in[15]; bo=(const float*)d_in[16];
        W1=(const float*)d_in[17]; b1=(const float*)d_in[18];
        W2=(const float*)d_in[19]; b2=(const float*)d_in[20];
    } else {
        Wq=(const float*)d_in[9];  Wk=(const float*)d_in[10];
        Wv=(const float*)d_in[11]; Wo=(const float*)d_in[12];
        W1=(const float*)d_in[13]; W2=(const float*)d_in[14];
        bq=(const float*)d_in[15]; bk=(const float*)d_in[16];
        bv=(const float*)d_in[17]; bo=(const float*)d_in[18];
        b1=(const float*)d_in[19]; b2=(const float*)d_in[20];
    }
    const float* g1  = (const float*)d_in[21];
    const float* be1 = (const float*)d_in[22];
    const float* g2  = (const float*)d_in[23];
    const float* be2 = (const float*)d_in[24];
    const float* clw = (const float*)d_in[25];
    const float* clb = (const float*)d_in[26];
    float* out = (float*)d_out;

    float *p_feat,*p_t,*p_q,*p_k,*p_v,*p_ao,*p_buf,*p_mid,*p_pe;
    float *p_bte,*p_btq,*p_btk,*p_btv,*p_bto,*p_bt1,*p_bt2;
    cudaGetSymbolAddress((void**)&p_feat, d_feat);
    cudaGetSymbolAddress((void**)&p_t,   d_t);
    cudaGetSymbolAddress((void**)&p_q,   d_q);
    cudaGetSymbolAddress((void**)&p_k,   d_k);
    cudaGetSymbolAddress((void**)&p_v,   d_v);
    cudaGetSymbolAddress((void**)&p_ao,  d_ao);
    cudaGetSymbolAddress((void**)&p_buf, d_buf);
    cudaGetSymbolAddress((void**)&p_mid, d_mid);
    cudaGetSymbolAddress((void**)&p_pe,  d_pe);
    cudaGetSymbolAddress((void**)&p_bte, d_bt_embed);
    cudaGetSymbolAddress((void**)&p_btq, d_btq);
    cudaGetSymbolAddress((void**)&p_btk, d_btk);
    cudaGetSymbolAddress((void**)&p_btv, d_btv);
    cudaGetSymbolAddress((void**)&p_bto, d_bto);
    cudaGetSymbolAddress((void**)&p_bt1, d_bt1);
    cudaGetSymbolAddress((void**)&p_bt2, d_bt2);

    cudaFuncSetAttribute(gemm_mma,     cudaFuncAttributeMaxDynamicSharedMemorySize, GSMEM);
    cudaFuncSetAttribute(gemm_mma_qkv, cudaFuncAttributeMaxDynamicSharedMemorySize, GSMEM);

    dim3 tb(32, 8);
    // weight transposes (tf32-rna): 4 launches
    transpose_tf32_qkvo<<<dim3(DM/32, DM/32, 16), tb>>>(Wq, Wk, Wv, Wo, p_btq, p_btk, p_btv, p_bto);
    transpose_tf32<<<dim3(FEATD/32, DM/32, 1), tb>>>(ew, p_bte, FEATD, DM);
    transpose_tf32<<<dim3(DM/32, DFF/32, 4), tb>>>(W1, p_bt1, DM, DFF);
    transpose_tf32<<<dim3(DFF/32, DM/32, 4), tb>>>(W2, p_bt2, DFF, DM);

    pe_kernel<<<(LW*(DM/2) + 255)/256, 256>>>();
    cnn_kernel<<<NWIN, 256>>>(x, cw0, cb0, cw1, cb1, cw2, cb2);

    // embed: t = tf32( relu(feat @ ew + eb) + pe )
    gemm_mma<<<dim3(DM/128, NWIN/64), 256, GSMEM>>>(p_feat, p_bte, eb, p_pe, p_t, FEATD, DM, 3);

    for (int i = 0; i < 4; i++) {
        gemm_mma_qkv<<<dim3(9, NWIN/64), 256, GSMEM>>>(
            p_t,
            p_btq + (size_t)i*DM*DM, p_btk + (size_t)i*DM*DM, p_btv + (size_t)i*DM*DM,
            bq + i*DM, bk + i*DM, bv + i*DM,
            p_q, p_k, p_v);

        attn_kernel<<<dim3(NB, HH), 128>>>(p_q, p_k, p_v, p_ao);

        gemm_mma<<<dim3(DM/128, NWIN/64), 256, GSMEM>>>(
            p_ao, p_bto + (size_t)i*DM*DM, bo + i*DM, p_t, p_buf, DM, DM, 2);
        ln_kernel<<<NWIN/8, 256>>>(p_buf, g1 + i*DM, be1 + i*DM, p_t);

        gemm_mma<<<dim3(DFF/128, NWIN/64), 256, GSMEM>>>(
            p_t, p_bt1 + (size_t)i*DFF*DM, b1 + i*DFF, nullptr, p_mid, DM, DFF, 1);
        gemm_mma<<<dim3(DM/128, NWIN/64), 256, GSMEM>>>(
            p_mid, p_bt2 + (size_t)i*DM*DFF, b2 + i*DM, p_t, p_buf, DFF, DM, 2);
        ln_kernel<<<NWIN/8, 256>>>(p_buf, g2 + i*DM, be2 + i*DM, p_t);
    }

    cls_kernel<<<NB, 384>>>(p_t, clw, clb, out);
}

// round 10
// speedup vs baseline: 4.5391x; 1.2288x over previous
#include <cuda_runtime.h>
#include <cuda_fp16.h>
#include <math.h>
#include <stdint.h>

// ---------------- problem constants ----------------
#define NB    64
#define LW    128
#define DM    384
#define HH    8
#define DFF   1536
#define NWIN  (NB*LW)     // 8192
#define FEATD 2048

// ---------------- scratch (device globals, alloc-free) ----------------
__device__ __half h_feat[NWIN*FEATD];
__device__ __half h_t  [NWIN*DM];
__device__ float  d_q  [NWIN*DM];
__device__ float  d_k  [NWIN*DM];
__device__ float  d_v  [NWIN*DM];
__device__ __half h_ao [NWIN*DM];
__device__ __half h_buf[NWIN*DM];
__device__ __half h_mid[NWIN*DFF];
__device__ float  d_pe [LW*DM];
__device__ __half h_bte[DM*FEATD];
__device__ __half h_btq[4][DM*DM];
__device__ __half h_btk[4][DM*DM];
__device__ __half h_btv[4][DM*DM];
__device__ __half h_bto[4][DM*DM];
__device__ __half h_bt1[4][DFF*DM];
__device__ __half h_bt2[4][DM*DFF];

// ---------------- helpers ----------------
__device__ __forceinline__ uint32_t smem_u32(const void* p) {
    uint32_t a;
    asm("{ .reg .u64 t; cvta.to.shared.u64 t, %1; cvt.u32.u64 %0, t; }" : "=r"(a) : "l"(p));
    return a;
}
__device__ __forceinline__ void cp16(uint32_t s, const void* g) {
    asm volatile("cp.async.cg.shared.global [%0], [%1], 16;" :: "r"(s), "l"(g));
}
__device__ __forceinline__ void cp_commit() { asm volatile("cp.async.commit_group;"); }
template<int N> __device__ __forceinline__ void cp_wait() {
    asm volatile("cp.async.wait_group %0;" :: "n"(N));
}
__device__ __forceinline__ void ldsm4(uint32_t* r, uint32_t addr) {
    asm volatile("ldmatrix.sync.aligned.m8n8.x4.shared.b16 {%0,%1,%2,%3}, [%4];"
        : "=r"(r[0]), "=r"(r[1]), "=r"(r[2]), "=r"(r[3]) : "r"(addr));
}
// m16n8k16 fp16 mma, fp32 accumulate
__device__ __forceinline__ void mma16(float* c, const uint32_t* a, uint32_t b0, uint32_t b1) {
    asm volatile("mma.sync.aligned.m16n8k16.row.col.f32.f16.f16.f32 "
        "{%0,%1,%2,%3}, {%4,%5,%6,%7}, {%8,%9}, {%0,%1,%2,%3};"
        : "+f"(c[0]), "+f"(c[1]), "+f"(c[2]), "+f"(c[3])
        : "r"(a[0]), "r"(a[1]), "r"(a[2]), "r"(a[3]), "r"(b0), "r"(b1));
}

// SMEM per stage: A [64][40] halfs + B [128][40] halfs (rows 32 -> pad 40 halfs = 80 B)
#define ROWB    80
#define ATILEB  (64*ROWB)      // 5120
#define BTILEB  (128*ROWB)     // 10240
#define STAGEB  (ATILEB+BTILEB) // 15360
#define GSMEM   (2*STAGEB)      // 30720

// ---------------- fp16 mma GEMM core: C tile 64x128, K chunks of 32 ----------------
// epi: 0=+bias ; 1=relu(+bias) ; 2=+bias+extra_half[m*ldc+c] ; 3=relu(+bias)+pe_f32[(m&127)*ldc+c]
// half_out: 1 -> __half C, 0 -> float C
__device__ __forceinline__ void gemm_core(
    const __half* __restrict__ A, const __half* __restrict__ BtBlk,
    const float* __restrict__ bias, const void* __restrict__ extra,
    void* __restrict__ C, int K, int ldc, int epi, int half_out, int row0, int col0)
{
    extern __shared__ float sm[];
    uint32_t sbase = smem_u32(sm);
    int tid = threadIdx.x;

    // loaders: rows of 32 halfs = 4 x 16B. A: 64 rows (1 xfer/thread), B: 128 rows (2/thread)
    int lrow = tid >> 2, lc = tid & 3;
    const __half* Ag  = A + (size_t)(row0 + lrow) * K + lc * 8;
    const __half* Bg0 = BtBlk + (size_t)lrow * K + lc * 8;
    const __half* Bg1 = BtBlk + (size_t)(lrow + 64) * K + lc * 8;
    uint32_t sA  = sbase + lrow * ROWB + lc * 16;
    uint32_t sB0 = sbase + ATILEB + lrow * ROWB + lc * 16;
    uint32_t sB1 = sB0 + 64 * ROWB;
    int nk = K >> 5;

    // prologue: chunk 0 -> slot 0
    cp16(sA,  Ag);
    cp16(sB0, Bg0);
    cp16(sB1, Bg1);
    cp_commit();

    int lane = tid & 31, w = tid >> 5, wm = w & 1, wn = w >> 1;
    // ldmatrix x4 lane addressing: rows (lane&15), k-half (lane>>4)
    uint32_t aoff = sbase + (wm * 32 + (lane & 15)) * ROWB + (lane >> 4) * 16;
    uint32_t boff = sbase + ATILEB + (wn * 32 + (lane & 15)) * ROWB + (lane >> 4) * 16;

    float c[2][4][4];
    #pragma unroll
    for (int i = 0; i < 2; i++)
        #pragma unroll
        for (int j = 0; j < 4; j++)
            #pragma unroll
            for (int q = 0; q < 4; q++) c[i][j][q] = 0.f;

    for (int kc = 0; kc < nk; kc++) {
        cp_wait<0>();
        __syncthreads();
        if (kc + 1 < nk) {
            uint32_t off = ((kc + 1) & 1) * STAGEB;
            int ho = (kc + 1) * 32;
            cp16(sA + off,  Ag + ho);
            cp16(sB0 + off, Bg0 + ho);
            cp16(sB1 + off, Bg1 + ho);
            cp_commit();
        }
        uint32_t st = (kc & 1) * STAGEB;
        uint32_t ab = aoff + st;
        uint32_t bb = boff + st;
        #pragma unroll
        for (int ks = 0; ks < 2; ks++) {           // two k16 steps per 32-chunk
            uint32_t af[2][4], bf[2][4];
            #pragma unroll
            for (int mf = 0; mf < 2; mf++)
                ldsm4(af[mf], ab + mf * 16 * ROWB + ks * 32);
            #pragma unroll
            for (int np = 0; np < 2; np++)
                ldsm4(bf[np], bb + np * 16 * ROWB + ks * 32);
            #pragma unroll
            for (int mf = 0; mf < 2; mf++)
                #pragma unroll
                for (int nf = 0; nf < 4; nf++) {
                    int np = nf >> 1, sub = nf & 1;
                    mma16(c[mf][nf], af[mf], bf[np][sub], bf[np][sub + 2]);
                }
        }
    }

    // epilogue
    #pragma unroll
    for (int mf = 0; mf < 2; mf++) {
        #pragma unroll
        for (int half = 0; half < 2; half++) {
            int r = row0 + wm * 32 + mf * 16 + (lane >> 2) + half * 8;
            #pragma unroll
            for (int nf = 0; nf < 4; nf++) {
                int col = col0 + wn * 32 + nf * 8 + (lane & 3) * 2;
                float v0 = c[mf][nf][half * 2 + 0] + bias[col];
                float v1 = c[mf][nf][half * 2 + 1] + bias[col + 1];
                if (epi == 1) { v0 = fmaxf(v0, 0.f); v1 = fmaxf(v1, 0.f); }
                else if (epi == 2) {
                    __half2 e = *(const __half2*)((const __half*)extra + (size_t)r * ldc + col);
                    v0 += __low2float(e); v1 += __high2float(e);
                } else if (epi == 3) {
                    const float* ex = (const float*)extra + (size_t)(r & (LW - 1)) * ldc;
                    v0 = fmaxf(v0, 0.f) + ex[col];
                    v1 = fmaxf(v1, 0.f) + ex[col + 1];
                }
                if (half_out)
                    *(__half2*)((__half*)C + (size_t)r * ldc + col) = __floats2half2_rn(v0, v1);
                else
                    *(float2*)((float*)C + (size_t)r * ldc + col) = make_float2(v0, v1);
            }
        }
    }
}

__global__ __launch_bounds__(256, 3) void gemm_h(
    const __half* __restrict__ A, const __half* __restrict__ Bt,
    const float* __restrict__ bias, const void* __restrict__ extra,
    void* __restrict__ C, int K, int N, int epi, int half_out)
{
    gemm_core(A, Bt + (size_t)blockIdx.x * 128 * K, bias, extra, C, K, N, epi, half_out,
              blockIdx.y * 64, blockIdx.x * 128);
}

__global__ __launch_bounds__(256, 3) void gemm_h_qkv(
    const __half* __restrict__ A,
    const __half* __restrict__ btq, const __half* __restrict__ btk, const __half* __restrict__ btv,
    const float* __restrict__ bqv, const float* __restrict__ bkv, const float* __restrict__ bvv,
    float* __restrict__ q, float* __restrict__ k, float* __restrict__ v)
{
    int sel = blockIdx.x / 3, j = blockIdx.x % 3;
    const __half* Bt   = sel == 0 ? btq : (sel == 1 ? btk : btv);
    const float* bias  = sel == 0 ? bqv : (sel == 1 ? bkv : bvv);
    float*       C     = sel == 0 ? q   : (sel == 1 ? k   : v);
    gemm_core(A, Bt + (size_t)j * 128 * DM, bias, nullptr, C, DM, DM, 0, 0,
              blockIdx.y * 64, j * 128);
}

// ---------------- batched weight transpose -> fp16: out[z][n][k] = h(in[z][k][n]) ----------------
__global__ void transpose_h(const float* __restrict__ in, __half* __restrict__ out, int Kd, int Nd)
{
    size_t mstride = (size_t)Kd * Nd;
    in  += blockIdx.z * mstride;
    out += blockIdx.z * mstride;
    __shared__ float tile[32][33];
    int kb = blockIdx.x * 32, nb = blockIdx.y * 32;
    int tx = threadIdx.x, ty = threadIdx.y;
    #pragma unroll
    for (int j = 0; j < 32; j += 8)
        tile[ty + j][tx] = in[(size_t)(kb + ty + j) * Nd + nb + tx];
    __syncthreads();
    #pragma unroll
    for (int j = 0; j < 32; j += 8)
        out[(size_t)(nb + ty + j) * Kd + kb + tx] = __float2half_rn(tile[tx][ty + j]);
}

// merged transpose for the 16 DM x DM attention weight matrices (z = sel*4 + layer)
__global__ void transpose_h_qkvo(
    const float* __restrict__ Wq, const float* __restrict__ Wk,
    const float* __restrict__ Wv, const float* __restrict__ Wo,
    __half* __restrict__ oq, __half* __restrict__ ok,
    __half* __restrict__ ov, __half* __restrict__ oo)
{
    int z = blockIdx.z, sel = z >> 2, layer = z & 3;
    const float* in = (sel == 0 ? Wq : sel == 1 ? Wk : sel == 2 ? Wv : Wo)
                      + (size_t)layer * DM * DM;
    __half* out = (sel == 0 ? oq : sel == 1 ? ok : sel == 2 ? ov : oo)
                  + (size_t)layer * DM * DM;
    __shared__ float tile[32][33];
    int kb = blockIdx.x * 32, nb = blockIdx.y * 32;
    int tx = threadIdx.x, ty = threadIdx.y;
    #pragma unroll
    for (int j = 0; j < 32; j += 8)
        tile[ty + j][tx] = in[(size_t)(kb + ty + j) * DM + nb + tx];
    __syncthreads();
    #pragma unroll
    for (int j = 0; j < 32; j += 8)
        out[(size_t)(nb + ty + j) * DM + kb + tx] = __float2half_rn(tile[tx][ty + j]);
}

// ---------------- positional encoding ----------------
__global__ void pe_kernel() {
    int idx = blockIdx.x * blockDim.x + threadIdx.x;
    if (idx >= LW * (DM / 2)) return;
    int l = idx / (DM / 2);
    int i = idx % (DM / 2);
    double ang = (double)l / pow(10000.0, (2.0 * i) / (double)DM);
    d_pe[l * DM + 2 * i]     = (float)sin(ang);
    d_pe[l * DM + 2 * i + 1] = (float)cos(ang);
}

// ---------------- fused CNN window encoder: one block per window ----------------
__global__ __launch_bounds__(256) void cnn_kernel(
    const float* __restrict__ x,
    const float* __restrict__ w0, const float* __restrict__ b0,
    const float* __restrict__ w1, const float* __restrict__ b1,
    const float* __restrict__ w2, const float* __restrict__ b2)
{
    __shared__ float sx[256];
    __shared__ float a0[4 * 128];
    __shared__ float a1[16 * 64];
    __shared__ float sw0[28];
    __shared__ float sw1[448];
    __shared__ float sw2t[112 * 64];     // [ci*7+k][c] transposed
    __shared__ float sb0[4], sb1[16], sb2[64];

    int win = blockIdx.x;
    int tid = threadIdx.x;

    sx[tid] = x[win * 256 + tid];
    if (tid < 28) sw0[tid] = w0[tid];
    if (tid < 4)  sb0[tid] = b0[tid];
    for (int i = tid; i < 448; i += 256) sw1[i] = w1[i];
    if (tid < 16) sb1[tid] = b1[tid];
    for (int i = tid; i < 7168; i += 256) {
        int c = i / 112, r = i % 112;
        sw2t[r * 64 + c] = w2[i];
    }
    if (tid < 64) sb2[tid] = b2[tid];
    __syncthreads();

    // stage 0: conv(1->4,k7,p3)+relu+pool2 : 256 -> 4x128
    for (int it = tid; it < 4 * 128; it += 256) {
        int c = it >> 7, p = it & 127;
        float acc0 = sb0[c], acc1 = sb0[c];
        #pragma unroll
        for (int k = 0; k < 7; k++) {
            float wv = sw0[c * 7 + k];
            int i0 = 2 * p + k - 3, i1 = i0 + 1;
            if (i0 >= 0 && i0 < 256) acc0 += sx[i0] * wv;
            if (i1 >= 0 && i1 < 256) acc1 += sx[i1] * wv;
        }
        a0[c * 128 + p] = fmaxf(fmaxf(acc0, acc1), 0.f);
    }
    __syncthreads();

    // stage 1: conv(4->16)+relu+pool : 4x128 -> 16x64
    for (int it = tid; it < 16 * 64; it += 256) {
        int c = it >> 6, p = it & 63;
        float acc0 = sb1[c], acc1 = sb1[c];
        for (int ci = 0; ci < 4; ci++) {
            const float* wrow = &sw1[(c * 4 + ci) * 7];
            const float* arow = &a0[ci * 128];
            #pragma unroll
            for (int k = 0; k < 7; k++) {
                float wv = wrow[k];
                int i0 = 2 * p + k - 3, i1 = i0 + 1;
                if (i0 >= 0 && i0 < 128) acc0 += arow[i0] * wv;
                if (i1 >= 0 && i1 < 128) acc1 += arow[i1] * wv;
            }
        }
        a1[c * 64 + p] = fmaxf(fmaxf(acc0, acc1), 0.f);
    }
    __syncthreads();

    // stage 2: conv(16->64)+relu+pool : 16x64 -> 64x32, register-blocked, half output
    {
        int c = tid & 63, g = tid >> 6;
        float acc0[8], acc1[8];
        #pragma unroll
        for (int p = 0; p < 8; p++) { acc0[p] = sb2[c]; acc1[p] = sb2[c]; }
        int base = 16 * g - 3;
        for (int ci = 0; ci < 16; ci++) {
            float xin[22];
            #pragma unroll
            for (int j = 0; j < 22; j++) {
                int idx = base + j;
                xin[j] = (idx >= 0 && idx < 64) ? a1[ci * 64 + idx] : 0.f;
            }
            float wv[7];
            #pragma unroll
            for (int k = 0; k < 7; k++) wv[k] = sw2t[(ci * 7 + k) * 64 + c];
            #pragma unroll
            for (int p = 0; p < 8; p++) {
                #pragma unroll
                for (int k = 0; k < 7; k++) {
                    acc0[p] += wv[k] * xin[2 * p + k];
                    acc1[p] += wv[k] * xin[2 * p + k + 1];
                }
            }
        }
        __half* dst = h_feat + (size_t)win * 2048 + c * 32 + g * 8;
        #pragma unroll
        for (int p = 0; p < 4; p++) {
            float e0 = fmaxf(fmaxf(acc0[2*p],   acc1[2*p]),   0.f);
            float e1 = fmaxf(fmaxf(acc0[2*p+1], acc1[2*p+1]), 0.f);
            *(__half2*)(dst + 2 * p) = __floats2half2_rn(e0, e1);
        }
    }
}

// ---------------- flash-style attention: one block per (n,h); fp32 q/k/v in, fp16 out ----------------
__global__ __launch_bounds__(128) void attn_kernel(
    const float* __restrict__ q, const float* __restrict__ k,
    const float* __restrict__ v, __half* __restrict__ o)
{
    __shared__ float Ks[2][32 * 48];
    __shared__ float Vs[2][32 * 48];

    int n = blockIdx.x, h = blockIdx.y;
    int tid = threadIdx.x;

    float4 qr[12];
    {
        const float4* qp = (const float4*)(q + (size_t)(n * 128 + tid) * DM + h * 48);
        #pragma unroll
        for (int j = 0; j < 12; j++) qr[j] = qp[j];
    }

    #define ATTN_ISSUE(c, b)                                                            \
        {                                                                               \
            _Pragma("unroll")                                                           \
            for (int f = tid; f < 384; f += 128) {                                      \
                int s = f / 12, j = f % 12;                                             \
                size_t gg = (size_t)(n * 128 + (c) * 32 + s) * DM + h * 48 + j * 4;     \
                cp16(smem_u32(&Ks[b][s * 48 + j * 4]), kk + gg);                        \
                cp16(smem_u32(&Vs[b][s * 48 + j * 4]), vv + gg);                        \
            }                                                                           \
            cp_commit();                                                                \
        }
    const float* kk = k;
    const float* vv = v;

    ATTN_ISSUE(0, 0);

    const float temp = 0.14433756729740643f;   // 1/sqrt(48)
    float m = -1e30f, ssum = 0.f;
    float4 acc[12];
    #pragma unroll
    for (int j = 0; j < 12; j++) acc[j] = make_float4(0.f, 0.f, 0.f, 0.f);

    for (int c = 0; c < 4; c++) {
        cp_wait<0>();
        __syncthreads();
        if (c < 3) ATTN_ISSUE(c + 1, (c + 1) & 1);
        int b = c & 1;

        float sc[32];
        float cm = -1e30f;
        #pragma unroll 4
        for (int s = 0; s < 32; s++) {
            const float4* kr = (const float4*)&Ks[b][s * 48];
            float d = 0.f;
            #pragma unroll
            for (int j = 0; j < 12; j++) {
                float4 a = qr[j], bb2 = kr[j];
                d += a.x * bb2.x + a.y * bb2.y + a.z * bb2.z + a.w * bb2.w;
            }
            d *= temp;
            sc[s] = d;
            cm = fmaxf(cm, d);
        }
        float nm = fmaxf(m, cm);
        float f = __expf(m - nm);
        ssum *= f;
        #pragma unroll
        for (int j = 0; j < 12; j++) {
            acc[j].x *= f; acc[j].y *= f; acc[j].z *= f; acc[j].w *= f;
        }
        #pragma unroll 4
        for (int s = 0; s < 32; s++) {
            float p = __expf(sc[s] - nm);
            ssum += p;
            const float4* vr = (const float4*)&Vs[b][s * 48];
            #pragma unroll
            for (int j = 0; j < 12; j++) {
                float4 bb2 = vr[j];
                acc[j].x += p * bb2.x; acc[j].y += p * bb2.y;
                acc[j].z += p * bb2.z; acc[j].w += p * bb2.w;
            }
        }
        m = nm;
    }

    float inv = 1.0f / ssum;
    __half* op = o + (size_t)(n * 128 + tid) * DM + h * 48;
    #pragma unroll
    for (int j = 0; j < 12; j++) {
        *(__half2*)(op + j * 4)     = __floats2half2_rn(acc[j].x * inv, acc[j].y * inv);
        *(__half2*)(op + j * 4 + 2) = __floats2half2_rn(acc[j].z * inv, acc[j].w * inv);
    }
}

// ---------------- layernorm (384): warp per row, 8 rows per block; half in/out ----------------
__global__ __launch_bounds__(256) void ln_kernel(
    const __half* __restrict__ in, const float* __restrict__ g,
    const float* __restrict__ b, __half* __restrict__ out)
{
    int row = blockIdx.x * 8 + (threadIdx.x >> 5);
    int lane = threadIdx.x & 31;
    const __half2* rp = (const __half2*)(in + (size_t)row * DM);
    int b2 = lane * 2;

    float2 f0 = __half22float2(rp[b2]),       f1 = __half22float2(rp[b2 + 1]);
    float2 f2 = __half22float2(rp[b2 + 64]),  f3 = __half22float2(rp[b2 + 65]);
    float2 f4 = __half22float2(rp[b2 + 128]), f5 = __half22float2(rp[b2 + 129]);

    float s = f0.x + f0.y + f1.x + f1.y + f2.x + f2.y + f3.x + f3.y + f4.x + f4.y + f5.x + f5.y;
    #pragma unroll
    for (int o2 = 16; o2; o2 >>= 1) s += __shfl_xor_sync(0xFFFFFFFFu, s, o2);
    float mean = s * (1.0f / 384.0f);

    float d0x = f0.x - mean, d0y = f0.y - mean, d1x = f1.x - mean, d1y = f1.y - mean;
    float d2x = f2.x - mean, d2y = f2.y - mean, d3x = f3.x - mean, d3y = f3.y - mean;
    float d4x = f4.x - mean, d4y = f4.y - mean, d5x = f5.x - mean, d5y = f5.y - mean;
    float q = d0x*d0x + d0y*d0y + d1x*d1x + d1y*d1y + d2x*d2x + d2y*d2y
            + d3x*d3x + d3y*d3y + d4x*d4x + d4y*d4y + d5x*d5x + d5y*d5y;
    #pragma unroll
    for (int o2 = 16; o2; o2 >>= 1) q += __shfl_xor_sync(0xFFFFFFFFu, q, o2);
    float inv = rsqrtf(q * (1.0f / 384.0f) + 1e-5f);

    float4 g0 = *(const float4*)(g + lane * 4);
    float4 g1 = *(const float4*)(g + lane * 4 + 128);
    float4 g2 = *(const float4*)(g + lane * 4 + 256);
    float4 b0 = *(const float4*)(b + lane * 4);
    float4 b1 = *(const float4*)(b + lane * 4 + 128);
    float4 b2v = *(const float4*)(b + lane * 4 + 256);

    __half2* op = (__half2*)(out + (size_t)row * DM);
    op[b2]       = __floats2half2_rn(d0x*inv*g0.x + b0.x,  d0y*inv*g0.y + b0.y);
    op[b2 + 1]   = __floats2half2_rn(d1x*inv*g0.z + b0.z,  d1y*inv*g0.w + b0.w);
    op[b2 + 64]  = __floats2half2_rn(d2x*inv*g1.x + b1.x,  d2y*inv*g1.y + b1.y);
    op[b2 + 65]  = __floats2half2_rn(d3x*inv*g1.z + b1.z,  d3y*inv*g1.w + b1.w);
    op[b2 + 128] = __floats2half2_rn(d4x*inv*g2.x + b2v.x, d4y*inv*g2.y + b2v.y);
    op[b2 + 129] = __floats2half2_rn(d5x*inv*g2.z + b2v.z, d5y*inv*g2.w + b2v.w);
}

// ---------------- mean-pool over L + classifier ----------------
__global__ __launch_bounds__(384) void cls_kernel(
    const __half* __restrict__ t, const float* __restrict__ w,
    const float* __restrict__ b, float* __restrict__ out)
{
    __shared__ float red[384];
    int n = blockIdx.x, d = threadIdx.x;
    float s = 0.f;
    for (int l = 0; l < 128; l++) s += __half2float(t[(size_t)(n * 128 + l) * DM + d]);
    red[d] = (s * (1.0f / 128.0f)) * w[d];
    __syncthreads();
    if (d < 128) red[d] += red[d + 128] + red[d + 256];
    __syncthreads();
    for (int st = 64; st > 0; st >>= 1) { if (d < st) red[d] += red[d + st]; __syncthreads(); }
    if (d == 0) out[n] = red[0] + b[0];
}

// ---------------- launcher ----------------
extern "C" void kernel_launch(void* const* d_in, const int* in_sizes, int n_in,
                              void* d_out, int out_size)
{
    const float* x   = (const float*)d_in[0];
    const float* cw0 = (const float*)d_in[1];
    const float* cb0 = (const float*)d_in[2];
    const float* cw1 = (const float*)d_in[3];
    const float* cb1 = (const float*)d_in[4];
    const float* cw2 = (const float*)d_in[5];
    const float* cb2 = (const float*)d_in[6];
    const float* ew  = (const float*)d_in[7];
    const float* eb  = (const float*)d_in[8];

    const float *Wq,*Wk,*Wv,*Wo,*W1,*W2,*bq,*bk,*bv,*bo,*b1,*b2;
    if (in_sizes[10] == 1536) {
        Wq=(const float*)d_in[9];  bq=(const float*)d_in[10];
        Wk=(const float*)d_in[11]; bk=(const float*)d_in[12];
        Wv=(const float*)d_in[13]; bv=(const float*)d_in[14];
        Wo=(const float*)d_in[15]; bo=(const float*)d_in[16];
        W1=(const float*)d_in[17]; b1=(const float*)d_in[18];
        W2=(const float*)d_in[19]; b2=(const float*)d_in[20];
    } else {
        Wq=(const float*)d_in[9];  Wk=(const float*)d_in[10];
        Wv=(const float*)d_in[11]; Wo=(const float*)d_in[12];
        W1=(const float*)d_in[13]; W2=(const float*)d_in[14];
        bq=(const float*)d_in[15]; bk=(const float*)d_in[16];
        bv=(const float*)d_in[17]; bo=(const float*)d_in[18];
        b1=(const float*)d_in[19]; b2=(const float*)d_in[20];
    }
    const float* g1  = (const float*)d_in[21];
    const float* be1 = (const float*)d_in[22];
    const float* g2  = (const float*)d_in[23];
    const float* be2 = (const float*)d_in[24];
    const float* clw = (const float*)d_in[25];
    const float* clb = (const float*)d_in[26];
    float* out = (float*)d_out;

    __half *p_feat,*p_t,*p_ao,*p_buf,*p_mid;
    __half *p_bte,*p_btq,*p_btk,*p_btv,*p_bto,*p_bt1,*p_bt2;
    float *p_q,*p_k,*p_v,*p_pe;
    cudaGetSymbolAddress((void**)&p_feat, h_feat);
    cudaGetSymbolAddress((void**)&p_t,   h_t);
    cudaGetSymbolAddress((void**)&p_q,   d_q);
    cudaGetSymbolAddress((void**)&p_k,   d_k);
    cudaGetSymbolAddress((void**)&p_v,   d_v);
    cudaGetSymbolAddress((void**)&p_ao,  h_ao);
    cudaGetSymbolAddress((void**)&p_buf, h_buf);
    cudaGetSymbolAddress((void**)&p_mid, h_mid);
    cudaGetSymbolAddress((void**)&p_pe,  d_pe);
    cudaGetSymbolAddress((void**)&p_bte, h_bte);
    cudaGetSymbolAddress((void**)&p_btq, h_btq);
    cudaGetSymbolAddress((void**)&p_btk, h_btk);
    cudaGetSymbolAddress((void**)&p_btv, h_btv);
    cudaGetSymbolAddress((void**)&p_bto, h_bto);
    cudaGetSymbolAddress((void**)&p_bt1, h_bt1);
    cudaGetSymbolAddress((void**)&p_bt2, h_bt2);

    dim3 tb(32, 8);
    // order: the 6th launch is the embed GEMM (so ncu -s 5 -c 1 captures a GEMM)
    pe_kernel<<<(LW*(DM/2) + 255)/256, 256>>>();                                   // 1
    cnn_kernel<<<NWIN, 256>>>(x, cw0, cb0, cw1, cb1, cw2, cb2);                    // 2
    transpose_h<<<dim3(FEATD/32, DM/32, 1), tb>>>(ew, p_bte, FEATD, DM);           // 3
    transpose_h_qkvo<<<dim3(DM/32, DM/32, 16), tb>>>(Wq, Wk, Wv, Wo,
                                                     p_btq, p_btk, p_btv, p_bto);  // 4
    transpose_h<<<dim3(DM/32, DFF/32, 4), tb>>>(W1, p_bt1, DM, DFF);               // 5
    // embed: t = h( relu(feat @ ew + eb) + pe )
    gemm_h<<<dim3(DM/128, NWIN/64), 256, GSMEM>>>(p_feat, p_bte, eb, p_pe,
                                                  p_t, FEATD, DM, 3, 1);           // 6
    transpose_h<<<dim3(DFF/32, DM/32, 4), tb>>>(W2, p_bt2, DFF, DM);               // 7

    for (int i = 0; i < 4; i++) {
        gemm_h_qkv<<<dim3(9, NWIN/64), 256, GSMEM>>>(
            p_t,
            p_btq + (size_t)i*DM*DM, p_btk + (size_t)i*DM*DM, p_btv + (size_t)i*DM*DM,
            bq + i*DM, bk + i*DM, bv + i*DM,
            p_q, p_k, p_v);

        attn_kernel<<<dim3(NB, HH), 128>>>(p_q, p_k, p_v, p_ao);

        gemm_h<<<dim3(DM/128, NWIN/64), 256, GSMEM>>>(
            p_ao, p_bto + (size_t)i*DM*DM, bo + i*DM, p_t, p_buf, DM, DM, 2, 1);
        ln_kernel<<<NWIN/8, 256>>>(p_buf, g1 + i*DM, be1 + i*DM, p_t);

        gemm_h<<<dim3(DFF/128, NWIN/64), 256, GSMEM>>>(
            p_t, p_bt1 + (size_t)i*DFF*DM, b1 + i*DFF, nullptr, p_mid, DM, DFF, 1, 1);
        gemm_h<<<dim3(DM/128, NWIN/64), 256, GSMEM>>>(
            p_mid, p_bt2 + (size_t)i*DM*DFF, b2 + i*DM, p_t, p_buf, DFF, DM, 2, 1);
        ln_kernel<<<NWIN/8, 256>>>(p_buf, g2 + i*DM, be2 + i*DM, p_t);
    }

    cls_kernel<<<NB, 384>>>(p_t, clw, clb, out);
}